// round 1
// baseline (speedup 1.0000x reference)
#include <cuda_runtime.h>
#include <math.h>

#define H 16
#define BATCH 4
#define SEQ 1024
#define DM 1024
#define DK 64
#define M_ROWS (BATCH*SEQ)        // 4096
#define OUT_OFF (M_ROWS*DM)       // 4,194,304 floats: 'out' first, then 'masked'

// Scratch (device globals; no allocation allowed)
__device__ float g_Q[H*BATCH*SEQ*DK];   // [h][b][s][dk]
__device__ float g_K[H*BATCH*SEQ*DK];
__device__ float g_V[H*BATCH*SEQ*DK];
__device__ float g_C[M_ROWS*DM];        // concat [b*s][h*dk]

// ---------------------------------------------------------------------------
// Kernel 1: per-head projections.  C[m, h*64+c] = sum_d X[m,d] * W[h,d,c]
// grid (DM/64, M_ROWS/64, 3), block 256.  BM=BN=64, BK=16, 4x4 per thread.
// ---------------------------------------------------------------------------
__global__ void proj_kernel(const float* __restrict__ q,
                            const float* __restrict__ k,
                            const float* __restrict__ v,
                            const float* __restrict__ Wq,
                            const float* __restrict__ Wk,
                            const float* __restrict__ Wv) {
    __shared__ float As[16][68];   // [k][m] transposed
    __shared__ float Bs[16][68];   // [k][n]

    const float* X; const float* W; float* O;
    if (blockIdx.z == 0)      { X = q; W = Wq; O = g_Q; }
    else if (blockIdx.z == 1) { X = k; W = Wk; O = g_K; }
    else                      { X = v; W = Wv; O = g_V; }

    const int n0 = blockIdx.x * 64;          // one head per N-tile
    const int m0 = blockIdx.y * 64;
    const int h  = n0 >> 6;
    const int tid = threadIdx.x;
    const int tx = tid & 15, ty = tid >> 4;

    const int lm  = tid >> 2;                // A-load row 0..63
    const int lk4 = (tid & 3) * 4;           // A-load k offset
    const int bk  = tid >> 6;                // B-load k group 0..3
    const int bc  = tid & 63;                // B-load col

    const float* Wh = W + h * (DM * DK);

    float acc[4][4];
    #pragma unroll
    for (int i = 0; i < 4; i++)
        #pragma unroll
        for (int j = 0; j < 4; j++) acc[i][j] = 0.f;

    for (int kt = 0; kt < DM; kt += 16) {
        float4 a = *reinterpret_cast<const float4*>(X + (size_t)(m0 + lm) * DM + kt + lk4);
        As[lk4 + 0][lm] = a.x; As[lk4 + 1][lm] = a.y;
        As[lk4 + 2][lm] = a.z; As[lk4 + 3][lm] = a.w;
        #pragma unroll
        for (int i = 0; i < 4; i++) {
            int kk = bk * 4 + i;
            Bs[kk][bc] = Wh[(size_t)(kt + kk) * DK + bc];
        }
        __syncthreads();
        #pragma unroll
        for (int kk = 0; kk < 16; kk++) {
            float4 av = *reinterpret_cast<const float4*>(&As[kk][ty * 4]);
            float4 bv = *reinterpret_cast<const float4*>(&Bs[kk][tx * 4]);
            float a4[4] = {av.x, av.y, av.z, av.w};
            float b4[4] = {bv.x, bv.y, bv.z, bv.w};
            #pragma unroll
            for (int i = 0; i < 4; i++)
                #pragma unroll
                for (int j = 0; j < 4; j++)
                    acc[i][j] += a4[i] * b4[j];
        }
        __syncthreads();
    }

    // store to [h][b][s][dk]
    #pragma unroll
    for (int i = 0; i < 4; i++) {
        int m = m0 + ty * 4 + i;
        int b = m >> 10;
        int s = m & 1023;
        float4 o = make_float4(acc[i][0], acc[i][1], acc[i][2], acc[i][3]);
        *reinterpret_cast<float4*>(O + ((size_t)((h * BATCH + b) * SEQ + s)) * DK + tx * 4) = o;
    }
}

// ---------------------------------------------------------------------------
// Kernel 2: fused attention per (qtile, h, b).
// Computes S = Q K^T * 0.125, applies mask, writes masked scores to d_out,
// online softmax, accumulates O = P V, writes O/l to concat buffer.
// grid (SEQ/64, H, BATCH), block 256, dynamic smem.
// ---------------------------------------------------------------------------
#define ATTN_SMEM_FLOATS (4*64*68 + 64*16 + 4*64)
#define ATTN_SMEM_BYTES  (ATTN_SMEM_FLOATS * 4)

__global__ void attn_kernel(const int* __restrict__ mask,
                            float* __restrict__ scores_out) {
    extern __shared__ float sm[];
    float* Qs  = sm;                 // [d][row]  stride 68
    float* Ks  = Qs + 64 * 68;       // [d][kcol] stride 68
    float* Vs  = Ks + 64 * 68;       // [kcol][d] stride 68
    float* Ps  = Vs + 64 * 68;       // [row][kcol] stride 68
    float* red = Ps + 64 * 68;       // [64][16]
    float* m_s  = red + 64 * 16;     // running max
    float* l_s  = m_s + 64;          // running sum
    float* mn_s = l_s + 64;          // new max
    float* c_s  = mn_s + 64;         // correction

    const int qt = blockIdx.x, h = blockIdx.y, b = blockIdx.z;
    const int tid = threadIdx.x, tx = tid & 15, ty = tid >> 4;

    const float* Qg = g_Q + ((size_t)((h * BATCH + b) * SEQ + qt * 64)) * DK;
    const float* Kg = g_K + ((size_t)((h * BATCH + b) * SEQ)) * DK;
    const float* Vg = g_V + ((size_t)((h * BATCH + b) * SEQ)) * DK;

    // load Q transposed: Qs[d][row]
    {
        int r = tid >> 2;
        #pragma unroll
        for (int j = 0; j < 4; j++) {
            int d0 = (tid & 3) * 16 + j * 4;
            float4 a = *reinterpret_cast<const float4*>(Qg + (size_t)r * DK + d0);
            Qs[(d0 + 0) * 68 + r] = a.x; Qs[(d0 + 1) * 68 + r] = a.y;
            Qs[(d0 + 2) * 68 + r] = a.z; Qs[(d0 + 3) * 68 + r] = a.w;
        }
    }
    if (tid < 64) { m_s[tid] = -INFINITY; l_s[tid] = 0.f; }

    float O[4][4];
    #pragma unroll
    for (int i = 0; i < 4; i++)
        #pragma unroll
        for (int j = 0; j < 4; j++) O[i][j] = 0.f;

    __syncthreads();

    for (int kt = 0; kt < SEQ; kt += 64) {
        // load K (transposed) and V (direct) tiles
        {
            int r = tid >> 2;
            #pragma unroll
            for (int j = 0; j < 4; j++) {
                int d0 = (tid & 3) * 16 + j * 4;
                float4 kv = *reinterpret_cast<const float4*>(Kg + (size_t)(kt + r) * DK + d0);
                Ks[(d0 + 0) * 68 + r] = kv.x; Ks[(d0 + 1) * 68 + r] = kv.y;
                Ks[(d0 + 2) * 68 + r] = kv.z; Ks[(d0 + 3) * 68 + r] = kv.w;
                float4 vv = *reinterpret_cast<const float4*>(Vg + (size_t)(kt + r) * DK + d0);
                *reinterpret_cast<float4*>(&Vs[r * 68 + d0]) = vv;
            }
        }
        __syncthreads();

        // S = Q K^T  (4x4 per thread)
        float s[4][4];
        #pragma unroll
        for (int i = 0; i < 4; i++)
            #pragma unroll
            for (int j = 0; j < 4; j++) s[i][j] = 0.f;
        #pragma unroll 8
        for (int d = 0; d < 64; d++) {
            float4 qv = *reinterpret_cast<const float4*>(&Qs[d * 68 + ty * 4]);
            float4 kv = *reinterpret_cast<const float4*>(&Ks[d * 68 + tx * 4]);
            float a4[4] = {qv.x, qv.y, qv.z, qv.w};
            float b4[4] = {kv.x, kv.y, kv.z, kv.w};
            #pragma unroll
            for (int i = 0; i < 4; i++)
                #pragma unroll
                for (int j = 0; j < 4; j++)
                    s[i][j] += a4[i] * b4[j];
        }

        // scale + mask + write masked scores; per-thread row maxes
        #pragma unroll
        for (int i = 0; i < 4; i++) {
            int qrow = qt * 64 + ty * 4 + i;
            const int* mrow = mask + (size_t)(b * SEQ + qrow) * SEQ + kt;
            int4 mv = *reinterpret_cast<const int4*>(mrow + tx * 4);
            s[i][0] = mv.x ? s[i][0] * 0.125f : -INFINITY;
            s[i][1] = mv.y ? s[i][1] * 0.125f : -INFINITY;
            s[i][2] = mv.z ? s[i][2] * 0.125f : -INFINITY;
            s[i][3] = mv.w ? s[i][3] * 0.125f : -INFINITY;
            float4 o = make_float4(s[i][0], s[i][1], s[i][2], s[i][3]);
            *reinterpret_cast<float4*>(scores_out +
                ((size_t)((h * BATCH + b) * SEQ + qrow)) * SEQ + kt + tx * 4) = o;
            float rm = fmaxf(fmaxf(s[i][0], s[i][1]), fmaxf(s[i][2], s[i][3]));
            red[(ty * 4 + i) * 16 + tx] = rm;
        }
        __syncthreads();

        if (tid < 64) {
            float rm = red[tid * 16];
            #pragma unroll
            for (int t = 1; t < 16; t++) rm = fmaxf(rm, red[tid * 16 + t]);
            float mo = m_s[tid];
            float mn = fmaxf(mo, rm);
            mn_s[tid] = mn;
            c_s[tid]  = __expf(mo - mn);
            m_s[tid]  = mn;
        }
        __syncthreads();

        // P = exp(S - mn), write Ps (row-major), partial row sums
        #pragma unroll
        for (int i = 0; i < 4; i++) {
            float mn = mn_s[ty * 4 + i];
            float p0 = __expf(s[i][0] - mn);
            float p1 = __expf(s[i][1] - mn);
            float p2 = __expf(s[i][2] - mn);
            float p3 = __expf(s[i][3] - mn);
            *reinterpret_cast<float4*>(&Ps[(ty * 4 + i) * 68 + tx * 4]) =
                make_float4(p0, p1, p2, p3);
            red[(ty * 4 + i) * 16 + tx] = p0 + p1 + p2 + p3;
        }
        __syncthreads();

        if (tid < 64) {
            float rs = 0.f;
            #pragma unroll
            for (int t = 0; t < 16; t++) rs += red[tid * 16 + t];
            l_s[tid] = l_s[tid] * c_s[tid] + rs;
        }
        __syncthreads();

        // rescale O, accumulate O += P V
        #pragma unroll
        for (int i = 0; i < 4; i++) {
            float c = c_s[ty * 4 + i];
            #pragma unroll
            for (int j = 0; j < 4; j++) O[i][j] *= c;
        }
        #pragma unroll 8
        for (int kc = 0; kc < 64; kc++) {
            float4 vv = *reinterpret_cast<const float4*>(&Vs[kc * 68 + tx * 4]);
            float v4[4] = {vv.x, vv.y, vv.z, vv.w};
            float p4[4];
            #pragma unroll
            for (int i = 0; i < 4; i++) p4[i] = Ps[(ty * 4 + i) * 68 + kc];
            #pragma unroll
            for (int i = 0; i < 4; i++)
                #pragma unroll
                for (int j = 0; j < 4; j++)
                    O[i][j] += p4[i] * v4[j];
        }
        __syncthreads();
    }

    // epilogue: O / l -> concat [b*s][h*64 + d]
    #pragma unroll
    for (int i = 0; i < 4; i++) {
        float inv = 1.0f / l_s[ty * 4 + i];
        int srow = qt * 64 + ty * 4 + i;
        float4 o = make_float4(O[i][0] * inv, O[i][1] * inv, O[i][2] * inv, O[i][3] * inv);
        *reinterpret_cast<float4*>(g_C + ((size_t)(b * SEQ + srow)) * DM + h * DK + tx * 4) = o;
    }
}

// ---------------------------------------------------------------------------
// Kernel 3: out = concat @ Wo.  grid (DM/64, M_ROWS/64), block 256.
// ---------------------------------------------------------------------------
__global__ void outproj_kernel(const float* __restrict__ Wo,
                               float* __restrict__ out) {
    __shared__ float As[16][68];
    __shared__ float Bs[16][68];

    const int n0 = blockIdx.x * 64;
    const int m0 = blockIdx.y * 64;
    const int tid = threadIdx.x;
    const int tx = tid & 15, ty = tid >> 4;

    const int lm  = tid >> 2;
    const int lk4 = (tid & 3) * 4;
    const int bk  = tid >> 6;
    const int bc  = tid & 63;

    float acc[4][4];
    #pragma unroll
    for (int i = 0; i < 4; i++)
        #pragma unroll
        for (int j = 0; j < 4; j++) acc[i][j] = 0.f;

    for (int kt = 0; kt < DM; kt += 16) {
        float4 a = *reinterpret_cast<const float4*>(g_C + (size_t)(m0 + lm) * DM + kt + lk4);
        As[lk4 + 0][lm] = a.x; As[lk4 + 1][lm] = a.y;
        As[lk4 + 2][lm] = a.z; As[lk4 + 3][lm] = a.w;
        #pragma unroll
        for (int i = 0; i < 4; i++) {
            int kk = bk * 4 + i;
            Bs[kk][bc] = Wo[(size_t)(kt + kk) * DM + n0 + bc];
        }
        __syncthreads();
        #pragma unroll
        for (int kk = 0; kk < 16; kk++) {
            float4 av = *reinterpret_cast<const float4*>(&As[kk][ty * 4]);
            float4 bv = *reinterpret_cast<const float4*>(&Bs[kk][tx * 4]);
            float a4[4] = {av.x, av.y, av.z, av.w};
            float b4[4] = {bv.x, bv.y, bv.z, bv.w};
            #pragma unroll
            for (int i = 0; i < 4; i++)
                #pragma unroll
                for (int j = 0; j < 4; j++)
                    acc[i][j] += a4[i] * b4[j];
        }
        __syncthreads();
    }

    #pragma unroll
    for (int i = 0; i < 4; i++) {
        int m = m0 + ty * 4 + i;
        float4 o = make_float4(acc[i][0], acc[i][1], acc[i][2], acc[i][3]);
        *reinterpret_cast<float4*>(out + (size_t)m * DM + n0 + tx * 4) = o;
    }
}

// ---------------------------------------------------------------------------
extern "C" void kernel_launch(void* const* d_in, const int* in_sizes, int n_in,
                              void* d_out, int out_size) {
    const float* q    = (const float*)d_in[0];
    const float* k    = (const float*)d_in[1];
    const float* v    = (const float*)d_in[2];
    const int*   mask = (const int*)  d_in[3];
    const float* Wq   = (const float*)d_in[4];
    const float* Wk   = (const float*)d_in[5];
    const float* Wv   = (const float*)d_in[6];
    const float* Wo   = (const float*)d_in[7];

    float* out    = (float*)d_out;
    float* scores = out + OUT_OFF;

    cudaFuncSetAttribute(attn_kernel,
                         cudaFuncAttributeMaxDynamicSharedMemorySize,
                         ATTN_SMEM_BYTES);

    proj_kernel<<<dim3(DM / 64, M_ROWS / 64, 3), 256>>>(q, k, v, Wq, Wk, Wv);
    attn_kernel<<<dim3(SEQ / 64, H, BATCH), 256, ATTN_SMEM_BYTES>>>(mask, scores);
    outproj_kernel<<<dim3(DM / 64, M_ROWS / 64), 256>>>(Wo, out);
}

// round 3
// speedup vs baseline: 1.5082x; 1.5082x over previous
#include <cuda_runtime.h>
#include <cuda_bf16.h>
#include <math.h>
#include <stdint.h>

#define H 16
#define BATCH 4
#define SEQ 1024
#define DM 1024
#define DK 64
#define M_ROWS (BATCH*SEQ)        // 4096
#define OUT_OFF (M_ROWS*DM)

using bf16 = __nv_bfloat16;

// ------------------------- device scratch (no allocs allowed) --------------
__device__ __align__(256) bf16  g_Ahi[3][M_ROWS*DM];   // split q,k,v inputs
__device__ __align__(256) bf16  g_Alo[3][M_ROWS*DM];
__device__ __align__(256) bf16  g_Whi[4][DM*DM];       // Wq,Wk,Wv,Wo as B[n][k]
__device__ __align__(256) bf16  g_Wlo[4][DM*DM];
__device__ __align__(256) float g_Qf[M_ROWS*DM];       // [b,s][h*64+dk]
__device__ __align__(256) float g_Kf[M_ROWS*DM];
__device__ __align__(256) float g_Vf[M_ROWS*DM];
__device__ __align__(256) float g_Cf[M_ROWS*DM];       // attn concat out
__device__ __align__(256) bf16  g_Chi[M_ROWS*DM];
__device__ __align__(256) bf16  g_Clo[M_ROWS*DM];

// ------------------------- PTX helpers (base-target legal) ------------------
__device__ __forceinline__ uint32_t smem_u32(const void* p) {
    uint32_t a;
    asm("{ .reg .u64 t; cvta.to.shared.u64 t, %1; cvt.u32.u64 %0, t; }"
        : "=r"(a) : "l"(p));
    return a;
}
#define CP_ASYNC16(s, g) \
    asm volatile("cp.async.cg.shared.global [%0], [%1], 16;" :: "r"(s), "l"(g))
#define CP_COMMIT() asm volatile("cp.async.commit_group;" ::: "memory")
#define CP_WAIT(n)  asm volatile("cp.async.wait_group %0;" :: "n"(n) : "memory")

__device__ __forceinline__ void ldm_x4(uint32_t* r, uint32_t addr) {
    asm volatile("ldmatrix.sync.aligned.m8n8.x4.shared.b16 {%0,%1,%2,%3}, [%4];"
        : "=r"(r[0]), "=r"(r[1]), "=r"(r[2]), "=r"(r[3]) : "r"(addr));
}
__device__ __forceinline__ void ldm_x2(uint32_t* r, uint32_t addr) {
    asm volatile("ldmatrix.sync.aligned.m8n8.x2.shared.b16 {%0,%1}, [%2];"
        : "=r"(r[0]), "=r"(r[1]) : "r"(addr));
}
__device__ __forceinline__ void mma16816(float* c, const uint32_t* a,
                                         const uint32_t* b) {
    asm volatile("mma.sync.aligned.m16n8k16.row.col.f32.bf16.bf16.f32 "
        "{%0,%1,%2,%3}, {%4,%5,%6,%7}, {%8,%9}, {%0,%1,%2,%3};"
        : "+f"(c[0]), "+f"(c[1]), "+f"(c[2]), "+f"(c[3])
        : "r"(a[0]), "r"(a[1]), "r"(a[2]), "r"(a[3]), "r"(b[0]), "r"(b[1]));
}

// ---------------------------------------------------------------------------
// Prep kernels: fp32 -> bf16 hi/lo splits
// ---------------------------------------------------------------------------
__global__ void split3_kernel(const float* __restrict__ a,
                              const float* __restrict__ b,
                              const float* __restrict__ c) {
    int z = blockIdx.z;
    const float* x = (z == 0) ? a : (z == 1) ? b : c;
    int i = blockIdx.x * 256 + threadIdx.x;
    float v = x[i];
    bf16 hi = __float2bfloat16(v);
    bf16 lo = __float2bfloat16(v - __bfloat162float(hi));
    g_Ahi[z][i] = hi; g_Alo[z][i] = lo;
}

__global__ void splitC_kernel() {
    int i = blockIdx.x * 256 + threadIdx.x;
    float v = g_Cf[i];
    bf16 hi = __float2bfloat16(v);
    bf16 lo = __float2bfloat16(v - __bfloat162float(hi));
    g_Chi[i] = hi; g_Clo[i] = lo;
}

// weights -> B[n][k] bf16 hi/lo. z<3: B[n][d] = W[h][d][kk], n=h*64+kk;
// z=3: B[n][k] = Wo[k][n]
__global__ void prep_w_kernel(const float* __restrict__ Wq,
                              const float* __restrict__ Wk,
                              const float* __restrict__ Wv,
                              const float* __restrict__ Wo) {
    int z = blockIdx.z;
    const float* W = (z == 0) ? Wq : (z == 1) ? Wk : (z == 2) ? Wv : Wo;
    int idx = blockIdx.x * 256 + threadIdx.x;
    int n = idx >> 10, d = idx & 1023;
    float v;
    if (z < 3) {
        int h = n >> 6, kk = n & 63;
        v = W[(size_t)(h * DM + d) * DK + kk];
    } else {
        v = W[(size_t)d * DM + n];
    }
    bf16 hi = __float2bfloat16(v);
    bf16 lo = __float2bfloat16(v - __bfloat162float(hi));
    g_Whi[z][idx] = hi; g_Wlo[z][idx] = lo;
}

// ---------------------------------------------------------------------------
// mma.sync split-bf16 GEMM:  C[4096,1024] = A[4096,1024] x B[n][k]^T
// BM=BN=128, BK=32, 256 threads (8 warps, 2x4), cp.async double buffer.
// smem row stride = 40 halves (80 B) -> conflict-free ldmatrix.
// ---------------------------------------------------------------------------
#define BK 32
#define NK (DM / BK)              // 32 k-chunks
#define TILE_B  (128 * 80)        // 10240 bytes per tile
#define STAGE_B (4 * TILE_B)      // Ah, Al, Bh, Bl
#define GEMM_SMEM (2 * STAGE_B)   // 81920 bytes

__global__ void __launch_bounds__(256, 1)
gemm_mma(int base_sel, float* __restrict__ out_ptr) {
    extern __shared__ char smem[];
    const int sel = base_sel + blockIdx.z;

    const bf16* Ah; const bf16* Al; float* C;
    if (sel == 0)      { Ah = g_Ahi[0]; Al = g_Alo[0]; C = g_Qf; }
    else if (sel == 1) { Ah = g_Ahi[1]; Al = g_Alo[1]; C = g_Kf; }
    else if (sel == 2) { Ah = g_Ahi[2]; Al = g_Alo[2]; C = g_Vf; }
    else               { Ah = g_Chi;    Al = g_Clo;    C = out_ptr; }
    const bf16* Bh = g_Whi[sel];
    const bf16* Bl = g_Wlo[sel];

    const uint32_t sb = smem_u32(smem);
    const int tid = threadIdx.x;
    const int wid = tid >> 5, lane = tid & 31;
    const int m0 = blockIdx.y * 128, n0 = blockIdx.x * 128;
    const int wm = (wid & 1) * 64;        // warp row offset
    const int wn = (wid >> 1) * 32;       // warp col offset

    // loader assignment: 4 tiles x 64 threads; 8 chunks of 16B each
    const int lt_tile = tid >> 6;         // 0=Ah 1=Al 2=Bh 3=Bl
    const int lt = tid & 63;
    const bf16* lsrc = (lt_tile == 0) ? Ah : (lt_tile == 1) ? Al
                     : (lt_tile == 2) ? Bh : Bl;
    const int lr0 = (lt_tile >= 2) ? n0 : m0;

    float acc[4][4][4];
    #pragma unroll
    for (int i = 0; i < 4; i++)
        #pragma unroll
        for (int j = 0; j < 4; j++)
            #pragma unroll
            for (int e = 0; e < 4; e++) acc[i][j][e] = 0.f;

    // prologue: load stage 0
    {
        const int k0 = 0;
        uint32_t tb = sb + lt_tile * TILE_B;
        #pragma unroll
        for (int c = 0; c < 8; c++) {
            int ch = lt + c * 64;
            int row = ch >> 2, kc = ch & 3;
            const bf16* g = lsrc + (size_t)(lr0 + row) * DM + k0 + kc * 8;
            CP_ASYNC16(tb + row * 80 + kc * 16, g);
        }
        CP_COMMIT();
    }

    for (int kch = 0; kch < NK; kch++) {
        if (kch + 1 < NK) {
            const int k0 = (kch + 1) * BK;
            uint32_t tb = sb + ((kch + 1) & 1) * STAGE_B + lt_tile * TILE_B;
            #pragma unroll
            for (int c = 0; c < 8; c++) {
                int ch = lt + c * 64;
                int row = ch >> 2, kc = ch & 3;
                const bf16* g = lsrc + (size_t)(lr0 + row) * DM + k0 + kc * 8;
                CP_ASYNC16(tb + row * 80 + kc * 16, g);
            }
            CP_COMMIT();
            CP_WAIT(1);
        } else {
            CP_WAIT(0);
        }
        __syncthreads();

        const uint32_t stage = sb + (kch & 1) * STAGE_B;
        const uint32_t sAh = stage;
        const uint32_t sAl = stage + TILE_B;
        const uint32_t sBh = stage + 2 * TILE_B;
        const uint32_t sBl = stage + 3 * TILE_B;

        #pragma unroll
        for (int ks = 0; ks < 2; ks++) {
            uint32_t ah[4][4], al[4][4], bh[4][2], bl[4][2];
            // A frags: rows wm+mi*16+(lane&15), col half sel by lane>>4
            #pragma unroll
            for (int mi = 0; mi < 4; mi++) {
                uint32_t ra = (uint32_t)(wm + mi * 16 + (lane & 15)) * 80
                            + ks * 32 + (lane >> 4) * 16;
                ldm_x4(ah[mi], sAh + ra);
                ldm_x4(al[mi], sAl + ra);
            }
            // B frags: rows wn+nj*8+(lane&7), k-half by (lane>>3)&1
            #pragma unroll
            for (int nj = 0; nj < 4; nj++) {
                uint32_t rb = (uint32_t)(wn + nj * 8 + (lane & 7)) * 80
                            + ks * 32 + ((lane >> 3) & 1) * 16;
                ldm_x2(bh[nj], sBh + rb);
                ldm_x2(bl[nj], sBl + rb);
            }
            #pragma unroll
            for (int mi = 0; mi < 4; mi++)
                #pragma unroll
                for (int nj = 0; nj < 4; nj++) {
                    mma16816(acc[mi][nj], ah[mi], bh[nj]);
                    mma16816(acc[mi][nj], ah[mi], bl[nj]);
                    mma16816(acc[mi][nj], al[mi], bh[nj]);
                }
        }
        __syncthreads();
    }

    // epilogue: direct fp32 stores
    #pragma unroll
    for (int mi = 0; mi < 4; mi++) {
        int row = m0 + wm + mi * 16 + (lane >> 2);
        #pragma unroll
        for (int nj = 0; nj < 4; nj++) {
            int col = n0 + wn + nj * 8 + (lane & 3) * 2;
            *reinterpret_cast<float2*>(C + (size_t)row * DM + col) =
                make_float2(acc[mi][nj][0], acc[mi][nj][1]);
            *reinterpret_cast<float2*>(C + (size_t)(row + 8) * DM + col) =
                make_float2(acc[mi][nj][2], acc[mi][nj][3]);
        }
    }
}

// ---------------------------------------------------------------------------
// Fused attention (SIMT) — Q/K/V in [b,s][h*64+dk] layout.
// ---------------------------------------------------------------------------
#define ATTN_SMEM_FLOATS (4*64*68 + 64*16 + 4*64)
#define ATTN_SMEM_BYTES  (ATTN_SMEM_FLOATS * 4)

__global__ void attn_kernel(const int* __restrict__ mask,
                            float* __restrict__ scores_out) {
    extern __shared__ float sm[];
    float* Qs  = sm;
    float* Ks  = Qs + 64 * 68;
    float* Vs  = Ks + 64 * 68;
    float* Ps  = Vs + 64 * 68;
    float* red = Ps + 64 * 68;
    float* m_s  = red + 64 * 16;
    float* l_s  = m_s + 64;
    float* mn_s = l_s + 64;
    float* c_s  = mn_s + 64;

    const int qt = blockIdx.x, h = blockIdx.y, b = blockIdx.z;
    const int tid = threadIdx.x, tx = tid & 15, ty = tid >> 4;

    const float* Qg = g_Qf + ((size_t)(b * SEQ + qt * 64)) * DM + h * DK;
    const float* Kg = g_Kf + ((size_t)(b * SEQ)) * DM + h * DK;
    const float* Vg = g_Vf + ((size_t)(b * SEQ)) * DM + h * DK;

    {
        int r = tid >> 2;
        #pragma unroll
        for (int j = 0; j < 4; j++) {
            int d0 = (tid & 3) * 16 + j * 4;
            float4 a = *reinterpret_cast<const float4*>(Qg + (size_t)r * DM + d0);
            Qs[(d0 + 0) * 68 + r] = a.x; Qs[(d0 + 1) * 68 + r] = a.y;
            Qs[(d0 + 2) * 68 + r] = a.z; Qs[(d0 + 3) * 68 + r] = a.w;
        }
    }
    if (tid < 64) { m_s[tid] = -INFINITY; l_s[tid] = 0.f; }

    float O[4][4];
    #pragma unroll
    for (int i = 0; i < 4; i++)
        #pragma unroll
        for (int j = 0; j < 4; j++) O[i][j] = 0.f;

    __syncthreads();

    for (int kt = 0; kt < SEQ; kt += 64) {
        {
            int r = tid >> 2;
            #pragma unroll
            for (int j = 0; j < 4; j++) {
                int d0 = (tid & 3) * 16 + j * 4;
                float4 kv = *reinterpret_cast<const float4*>(Kg + (size_t)(kt + r) * DM + d0);
                Ks[(d0 + 0) * 68 + r] = kv.x; Ks[(d0 + 1) * 68 + r] = kv.y;
                Ks[(d0 + 2) * 68 + r] = kv.z; Ks[(d0 + 3) * 68 + r] = kv.w;
                float4 vv = *reinterpret_cast<const float4*>(Vg + (size_t)(kt + r) * DM + d0);
                *reinterpret_cast<float4*>(&Vs[r * 68 + d0]) = vv;
            }
        }
        __syncthreads();

        float s[4][4];
        #pragma unroll
        for (int i = 0; i < 4; i++)
            #pragma unroll
            for (int j = 0; j < 4; j++) s[i][j] = 0.f;
        #pragma unroll 8
        for (int d = 0; d < 64; d++) {
            float4 qv = *reinterpret_cast<const float4*>(&Qs[d * 68 + ty * 4]);
            float4 kv = *reinterpret_cast<const float4*>(&Ks[d * 68 + tx * 4]);
            float a4[4] = {qv.x, qv.y, qv.z, qv.w};
            float b4[4] = {kv.x, kv.y, kv.z, kv.w};
            #pragma unroll
            for (int i = 0; i < 4; i++)
                #pragma unroll
                for (int j = 0; j < 4; j++)
                    s[i][j] += a4[i] * b4[j];
        }

        #pragma unroll
        for (int i = 0; i < 4; i++) {
            int qrow = qt * 64 + ty * 4 + i;
            const int* mrow = mask + (size_t)(b * SEQ + qrow) * SEQ + kt;
            int4 mv = *reinterpret_cast<const int4*>(mrow + tx * 4);
            s[i][0] = mv.x ? s[i][0] * 0.125f : -INFINITY;
            s[i][1] = mv.y ? s[i][1] * 0.125f : -INFINITY;
            s[i][2] = mv.z ? s[i][2] * 0.125f : -INFINITY;
            s[i][3] = mv.w ? s[i][3] * 0.125f : -INFINITY;
            float4 o = make_float4(s[i][0], s[i][1], s[i][2], s[i][3]);
            *reinterpret_cast<float4*>(scores_out +
                ((size_t)((h * BATCH + b) * SEQ + qrow)) * SEQ + kt + tx * 4) = o;
            float rm = fmaxf(fmaxf(s[i][0], s[i][1]), fmaxf(s[i][2], s[i][3]));
            red[(ty * 4 + i) * 16 + tx] = rm;
        }
        __syncthreads();

        if (tid < 64) {
            float rm = red[tid * 16];
            #pragma unroll
            for (int t = 1; t < 16; t++) rm = fmaxf(rm, red[tid * 16 + t]);
            float mo = m_s[tid];
            float mn = fmaxf(mo, rm);
            mn_s[tid] = mn;
            c_s[tid]  = __expf(mo - mn);
            m_s[tid]  = mn;
        }
        __syncthreads();

        #pragma unroll
        for (int i = 0; i < 4; i++) {
            float mn = mn_s[ty * 4 + i];
            float p0 = __expf(s[i][0] - mn);
            float p1 = __expf(s[i][1] - mn);
            float p2 = __expf(s[i][2] - mn);
            float p3 = __expf(s[i][3] - mn);
            *reinterpret_cast<float4*>(&Ps[(ty * 4 + i) * 68 + tx * 4]) =
                make_float4(p0, p1, p2, p3);
            red[(ty * 4 + i) * 16 + tx] = p0 + p1 + p2 + p3;
        }
        __syncthreads();

        if (tid < 64) {
            float rs = 0.f;
            #pragma unroll
            for (int t = 0; t < 16; t++) rs += red[tid * 16 + t];
            l_s[tid] = l_s[tid] * c_s[tid] + rs;
        }
        __syncthreads();

        #pragma unroll
        for (int i = 0; i < 4; i++) {
            float c = c_s[ty * 4 + i];
            #pragma unroll
            for (int j = 0; j < 4; j++) O[i][j] *= c;
        }
        #pragma unroll 8
        for (int kc = 0; kc < 64; kc++) {
            float4 vv = *reinterpret_cast<const float4*>(&Vs[kc * 68 + tx * 4]);
            float v4[4] = {vv.x, vv.y, vv.z, vv.w};
            float p4[4];
            #pragma unroll
            for (int i = 0; i < 4; i++) p4[i] = Ps[(ty * 4 + i) * 68 + kc];
            #pragma unroll
            for (int i = 0; i < 4; i++)
                #pragma unroll
                for (int j = 0; j < 4; j++)
                    O[i][j] += p4[i] * v4[j];
        }
        __syncthreads();
    }

    #pragma unroll
    for (int i = 0; i < 4; i++) {
        float inv = 1.0f / l_s[ty * 4 + i];
        int srow = qt * 64 + ty * 4 + i;
        float4 o = make_float4(O[i][0] * inv, O[i][1] * inv, O[i][2] * inv, O[i][3] * inv);
        *reinterpret_cast<float4*>(g_Cf + ((size_t)(b * SEQ + srow)) * DM + h * DK + tx * 4) = o;
    }
}

// ---------------------------------------------------------------------------
extern "C" void kernel_launch(void* const* d_in, const int* in_sizes, int n_in,
                              void* d_out, int out_size) {
    const float* q    = (const float*)d_in[0];
    const float* k    = (const float*)d_in[1];
    const float* v    = (const float*)d_in[2];
    const int*   mask = (const int*)  d_in[3];
    const float* Wq   = (const float*)d_in[4];
    const float* Wk   = (const float*)d_in[5];
    const float* Wv   = (const float*)d_in[6];
    const float* Wo   = (const float*)d_in[7];

    float* out    = (float*)d_out;
    float* scores = out + OUT_OFF;

    cudaFuncSetAttribute(attn_kernel,
                         cudaFuncAttributeMaxDynamicSharedMemorySize,
                         ATTN_SMEM_BYTES);
    cudaFuncSetAttribute(gemm_mma,
                         cudaFuncAttributeMaxDynamicSharedMemorySize,
                         GEMM_SMEM);

    split3_kernel<<<dim3(M_ROWS * DM / 256, 1, 3), 256>>>(q, k, v);
    prep_w_kernel<<<dim3(DM * DM / 256, 1, 4), 256>>>(Wq, Wk, Wv, Wo);
    gemm_mma<<<dim3(DM / 128, M_ROWS / 128, 3), 256, GEMM_SMEM>>>(0, nullptr);
    attn_kernel<<<dim3(SEQ / 64, H, BATCH), 256, ATTN_SMEM_BYTES>>>(mask, scores);
    splitC_kernel<<<M_ROWS * DM / 256, 256>>>();
    gemm_mma<<<dim3(DM / 128, M_ROWS / 128, 1), 256, GEMM_SMEM>>>(3, out);
}

// round 4
// speedup vs baseline: 2.0974x; 1.3906x over previous
#include <cuda_runtime.h>
#include <cuda_bf16.h>
#include <math.h>
#include <stdint.h>

#define H 16
#define BATCH 4
#define SEQ 1024
#define DM 1024
#define DK 64
#define M_ROWS (BATCH*SEQ)        // 4096
#define OUT_OFF (M_ROWS*DM)

using bf16 = __nv_bfloat16;

// ------------------------- device scratch (no allocs allowed) --------------
__device__ __align__(256) bf16  g_Ahi[3][M_ROWS*DM];   // split q,k,v inputs
__device__ __align__(256) bf16  g_Alo[3][M_ROWS*DM];
__device__ __align__(256) bf16  g_Whi[4][DM*DM];       // weights as B[n][k]
__device__ __align__(256) bf16  g_Wlo[4][DM*DM];
__device__ __align__(256) bf16  g_Qhi[M_ROWS*DM];      // [b,s][h*64+dk]
__device__ __align__(256) bf16  g_Qlo[M_ROWS*DM];
__device__ __align__(256) bf16  g_Khi[M_ROWS*DM];
__device__ __align__(256) bf16  g_Klo[M_ROWS*DM];
__device__ __align__(256) bf16  g_Vhi[M_ROWS*DM];
__device__ __align__(256) bf16  g_Vlo[M_ROWS*DM];
__device__ __align__(256) bf16  g_Vthi[H*BATCH*DK*SEQ]; // [h][b][dk][s]
__device__ __align__(256) bf16  g_Vtlo[H*BATCH*DK*SEQ];
__device__ __align__(256) bf16  g_Chi[M_ROWS*DM];      // attn concat out
__device__ __align__(256) bf16  g_Clo[M_ROWS*DM];

// ------------------------- PTX helpers (base-target legal) ------------------
__device__ __forceinline__ uint32_t smem_u32(const void* p) {
    uint32_t a;
    asm("{ .reg .u64 t; cvta.to.shared.u64 t, %1; cvt.u32.u64 %0, t; }"
        : "=r"(a) : "l"(p));
    return a;
}
#define CP_ASYNC16(s, g) \
    asm volatile("cp.async.cg.shared.global [%0], [%1], 16;" :: "r"(s), "l"(g))
#define CP_COMMIT() asm volatile("cp.async.commit_group;" ::: "memory")
#define CP_WAIT(n)  asm volatile("cp.async.wait_group %0;" :: "n"(n) : "memory")

__device__ __forceinline__ void ldm_x4(uint32_t* r, uint32_t addr) {
    asm volatile("ldmatrix.sync.aligned.m8n8.x4.shared.b16 {%0,%1,%2,%3}, [%4];"
        : "=r"(r[0]), "=r"(r[1]), "=r"(r[2]), "=r"(r[3]) : "r"(addr));
}
__device__ __forceinline__ void ldm_x2(uint32_t* r, uint32_t addr) {
    asm volatile("ldmatrix.sync.aligned.m8n8.x2.shared.b16 {%0,%1}, [%2];"
        : "=r"(r[0]), "=r"(r[1]) : "r"(addr));
}
__device__ __forceinline__ void mma16816(float* c, const uint32_t* a,
                                         const uint32_t* b) {
    asm volatile("mma.sync.aligned.m16n8k16.row.col.f32.bf16.bf16.f32 "
        "{%0,%1,%2,%3}, {%4,%5,%6,%7}, {%8,%9}, {%0,%1,%2,%3};"
        : "+f"(c[0]), "+f"(c[1]), "+f"(c[2]), "+f"(c[3])
        : "r"(a[0]), "r"(a[1]), "r"(a[2]), "r"(a[3]), "r"(b[0]), "r"(b[1]));
}
__device__ __forceinline__ void split_pack(float a, float b,
                                           uint32_t& hi, uint32_t& lo) {
    __nv_bfloat162 h2 = __floats2bfloat162_rn(a, b);
    float ra = a - __bfloat162float(h2.x);
    float rb = b - __bfloat162float(h2.y);
    __nv_bfloat162 l2 = __floats2bfloat162_rn(ra, rb);
    hi = *reinterpret_cast<uint32_t*>(&h2);
    lo = *reinterpret_cast<uint32_t*>(&l2);
}

// ---------------------------------------------------------------------------
// Prep: fp32 -> bf16 hi/lo split for q,k,v inputs (coalesced)
// ---------------------------------------------------------------------------
__global__ void split3_kernel(const float* __restrict__ a,
                              const float* __restrict__ b,
                              const float* __restrict__ c) {
    int z = blockIdx.z;
    const float* x = (z == 0) ? a : (z == 1) ? b : c;
    int i = blockIdx.x * 256 + threadIdx.x;
    float v = x[i];
    bf16 hi = __float2bfloat16(v);
    bf16 lo = __float2bfloat16(v - __bfloat162float(hi));
    g_Ahi[z][i] = hi; g_Alo[z][i] = lo;
}

// ---------------------------------------------------------------------------
// Prep: weights -> B[n][k] bf16 hi/lo, smem-transposed (coalesced).
// z<3: out[n=h*64+kk][k] = W[h][k][kk];  z=3: out[n][k] = Wo[k][n]
// grid (16 ktile, 16 h|ntile, 4 z), block 256
// ---------------------------------------------------------------------------
__global__ void prep_w_kernel(const float* __restrict__ Wq,
                              const float* __restrict__ Wk,
                              const float* __restrict__ Wv,
                              const float* __restrict__ Wo) {
    __shared__ float ws[64][65];
    const int z = blockIdx.z;
    const float* W = (z == 0) ? Wq : (z == 1) ? Wk : (z == 2) ? Wv : Wo;
    const int t = threadIdx.x;
    const int k0 = blockIdx.x * 64;
    const int nb = blockIdx.y;

    #pragma unroll
    for (int i = 0; i < 4; i++) {
        int id = t + i * 256;
        int row = id >> 4, c4 = id & 15;
        const float* src = (z < 3)
            ? W + (size_t)nb * 65536 + (size_t)(k0 + row) * 64 + c4 * 4
            : W + (size_t)(k0 + row) * DM + nb * 64 + c4 * 4;
        float4 v = *reinterpret_cast<const float4*>(src);
        ws[row][c4 * 4 + 0] = v.x; ws[row][c4 * 4 + 1] = v.y;
        ws[row][c4 * 4 + 2] = v.z; ws[row][c4 * 4 + 3] = v.w;
    }
    __syncthreads();

    const int kk = t >> 2, kg = t & 3;
    uint32_t hi[8], lo[8];
    #pragma unroll
    for (int j = 0; j < 8; j++)
        split_pack(ws[kg * 16 + 2 * j][kk], ws[kg * 16 + 2 * j + 1][kk],
                   hi[j], lo[j]);
    size_t off = (size_t)(nb * 64 + kk) * DM + k0 + kg * 16;
    uint16_t* dh = (uint16_t*)g_Whi[z];
    uint16_t* dl = (uint16_t*)g_Wlo[z];
    *reinterpret_cast<uint4*>(dh + off)     = make_uint4(hi[0], hi[1], hi[2], hi[3]);
    *reinterpret_cast<uint4*>(dh + off + 8) = make_uint4(hi[4], hi[5], hi[6], hi[7]);
    *reinterpret_cast<uint4*>(dl + off)     = make_uint4(lo[0], lo[1], lo[2], lo[3]);
    *reinterpret_cast<uint4*>(dl + off + 8) = make_uint4(lo[4], lo[5], lo[6], lo[7]);
}

// ---------------------------------------------------------------------------
// Prep: V [b,s][h*64+dk] bf16 hi/lo -> Vt [h][b][dk][s].  grid (16, 64)
// ---------------------------------------------------------------------------
__global__ void vt_kernel() {
    __shared__ uint16_t tile[2][64][72];
    const int t = threadIdx.x;
    const int h = blockIdx.y >> 2, b = blockIdx.y & 3, s0 = blockIdx.x * 64;

    #pragma unroll
    for (int i = 0; i < 4; i++) {
        int id = t + i * 256;
        int z = id >> 9, rid = id & 511;
        int row = rid >> 3, c8 = rid & 7;
        const uint16_t* src = (const uint16_t*)(z ? g_Vlo : g_Vhi);
        uint4 v = *reinterpret_cast<const uint4*>(
            src + (size_t)(b * SEQ + s0 + row) * DM + h * DK + c8 * 8);
        *reinterpret_cast<uint4*>(&tile[z][row][c8 * 8]) = v;
    }
    __syncthreads();
    #pragma unroll
    for (int i = 0; i < 4; i++) {
        int id = t + i * 256;
        int z = id >> 9, rid = id & 511;
        int dk = rid >> 3, sc = rid & 7;
        uint32_t u[4];
        #pragma unroll
        for (int j = 0; j < 4; j++) {
            uint32_t a = tile[z][sc * 8 + 2 * j][dk];
            uint32_t c = tile[z][sc * 8 + 2 * j + 1][dk];
            u[j] = a | (c << 16);
        }
        uint16_t* dst = (uint16_t*)(z ? g_Vtlo : g_Vthi);
        *reinterpret_cast<uint4*>(
            dst + (size_t)((h * BATCH + b) * DK + dk) * SEQ + s0 + sc * 8) =
            make_uint4(u[0], u[1], u[2], u[3]);
    }
}

// ---------------------------------------------------------------------------
// mma.sync split-bf16 GEMM:  C[4096,1024] = A x B[n][k]^T
// sel 0..2 -> split bf16 epilogue (Q/K/V); sel 3 -> fp32 out.
// ---------------------------------------------------------------------------
#define BK 32
#define NKC (DM / BK)
#define TILE_B  (128 * 80)
#define STAGE_B (4 * TILE_B)
#define GEMM_SMEM (2 * STAGE_B)   // 81920

__global__ void __launch_bounds__(256, 1)
gemm_mma(int base_sel, float* __restrict__ out_ptr) {
    extern __shared__ char smem[];
    const int sel = base_sel + blockIdx.z;

    const bf16* Ah; const bf16* Al;
    bf16* Oh = nullptr; bf16* Ol = nullptr;
    if (sel == 0)      { Ah = g_Ahi[0]; Al = g_Alo[0]; Oh = g_Qhi; Ol = g_Qlo; }
    else if (sel == 1) { Ah = g_Ahi[1]; Al = g_Alo[1]; Oh = g_Khi; Ol = g_Klo; }
    else if (sel == 2) { Ah = g_Ahi[2]; Al = g_Alo[2]; Oh = g_Vhi; Ol = g_Vlo; }
    else               { Ah = g_Chi;    Al = g_Clo; }
    const bf16* Bh = g_Whi[sel];
    const bf16* Bl = g_Wlo[sel];

    const uint32_t sb = smem_u32(smem);
    const int tid = threadIdx.x;
    const int wid = tid >> 5, lane = tid & 31;
    const int m0 = blockIdx.y * 128, n0 = blockIdx.x * 128;
    const int wm = (wid & 1) * 64;
    const int wn = (wid >> 1) * 32;

    const int lt_tile = tid >> 6;
    const int lt = tid & 63;
    const bf16* lsrc = (lt_tile == 0) ? Ah : (lt_tile == 1) ? Al
                     : (lt_tile == 2) ? Bh : Bl;
    const int lr0 = (lt_tile >= 2) ? n0 : m0;

    float acc[4][4][4];
    #pragma unroll
    for (int i = 0; i < 4; i++)
        #pragma unroll
        for (int j = 0; j < 4; j++)
            #pragma unroll
            for (int e = 0; e < 4; e++) acc[i][j][e] = 0.f;

    {
        uint32_t tb = sb + lt_tile * TILE_B;
        #pragma unroll
        for (int c = 0; c < 8; c++) {
            int ch = lt + c * 64;
            int row = ch >> 2, kc = ch & 3;
            CP_ASYNC16(tb + row * 80 + kc * 16,
                       lsrc + (size_t)(lr0 + row) * DM + kc * 8);
        }
        CP_COMMIT();
    }

    for (int kch = 0; kch < NKC; kch++) {
        if (kch + 1 < NKC) {
            const int k0 = (kch + 1) * BK;
            uint32_t tb = sb + ((kch + 1) & 1) * STAGE_B + lt_tile * TILE_B;
            #pragma unroll
            for (int c = 0; c < 8; c++) {
                int ch = lt + c * 64;
                int row = ch >> 2, kc = ch & 3;
                CP_ASYNC16(tb + row * 80 + kc * 16,
                           lsrc + (size_t)(lr0 + row) * DM + k0 + kc * 8);
            }
            CP_COMMIT();
            CP_WAIT(1);
        } else {
            CP_WAIT(0);
        }
        __syncthreads();

        const uint32_t stage = sb + (kch & 1) * STAGE_B;
        const uint32_t sAh = stage;
        const uint32_t sAl = stage + TILE_B;
        const uint32_t sBh = stage + 2 * TILE_B;
        const uint32_t sBl = stage + 3 * TILE_B;

        #pragma unroll
        for (int ks = 0; ks < 2; ks++) {
            uint32_t ah[4][4], al[4][4], bh[4][2], bl[4][2];
            #pragma unroll
            for (int mi = 0; mi < 4; mi++) {
                uint32_t ra = (uint32_t)(wm + mi * 16 + (lane & 15)) * 80
                            + ks * 32 + (lane >> 4) * 16;
                ldm_x4(ah[mi], sAh + ra);
                ldm_x4(al[mi], sAl + ra);
            }
            #pragma unroll
            for (int nj = 0; nj < 4; nj++) {
                uint32_t rb = (uint32_t)(wn + nj * 8 + (lane & 7)) * 80
                            + ks * 32 + ((lane >> 3) & 1) * 16;
                ldm_x2(bh[nj], sBh + rb);
                ldm_x2(bl[nj], sBl + rb);
            }
            #pragma unroll
            for (int mi = 0; mi < 4; mi++)
                #pragma unroll
                for (int nj = 0; nj < 4; nj++) {
                    mma16816(acc[mi][nj], ah[mi], bh[nj]);
                    mma16816(acc[mi][nj], ah[mi], bl[nj]);
                    mma16816(acc[mi][nj], al[mi], bh[nj]);
                }
        }
        __syncthreads();
    }

    if (sel < 3) {
        uint16_t* oh = (uint16_t*)Oh;
        uint16_t* ol = (uint16_t*)Ol;
        #pragma unroll
        for (int mi = 0; mi < 4; mi++) {
            int row = m0 + wm + mi * 16 + (lane >> 2);
            #pragma unroll
            for (int nj = 0; nj < 4; nj++) {
                int col = n0 + wn + nj * 8 + (lane & 3) * 2;
                uint32_t h0, l0v, h1, l1v;
                split_pack(acc[mi][nj][0], acc[mi][nj][1], h0, l0v);
                split_pack(acc[mi][nj][2], acc[mi][nj][3], h1, l1v);
                *reinterpret_cast<uint32_t*>(oh + (size_t)row * DM + col) = h0;
                *reinterpret_cast<uint32_t*>(ol + (size_t)row * DM + col) = l0v;
                *reinterpret_cast<uint32_t*>(oh + (size_t)(row + 8) * DM + col) = h1;
                *reinterpret_cast<uint32_t*>(ol + (size_t)(row + 8) * DM + col) = l1v;
            }
        }
    } else {
        #pragma unroll
        for (int mi = 0; mi < 4; mi++) {
            int row = m0 + wm + mi * 16 + (lane >> 2);
            #pragma unroll
            for (int nj = 0; nj < 4; nj++) {
                int col = n0 + wn + nj * 8 + (lane & 3) * 2;
                *reinterpret_cast<float2*>(out_ptr + (size_t)row * DM + col) =
                    make_float2(acc[mi][nj][0], acc[mi][nj][1]);
                *reinterpret_cast<float2*>(out_ptr + (size_t)(row + 8) * DM + col) =
                    make_float2(acc[mi][nj][2], acc[mi][nj][3]);
            }
        }
    }
}

// ---------------------------------------------------------------------------
// Tensor-core fused attention.  grid (8, 16, 4), block 256 (8 warps x 16 rows).
// ---------------------------------------------------------------------------
#define SQH 0
#define SQL 18432
#define STAGE0 36864
#define STAGE_SZ 36864
#define OKH 0
#define OKL 9216
#define OVH 18432
#define OVL 27648
#define ATTN_SMEM 110592
#define NEGINF (-INFINITY)

__device__ __forceinline__ void issue_kv(uint32_t stg, int kt0, int h, int b,
                                         int tid) {
    const int tile = tid >> 6, lt = tid & 63;
    if (tile < 2) {
        const bf16* s = tile ? g_Klo : g_Khi;
        uint32_t dstb = stg + (tile ? OKL : OKH);
        #pragma unroll
        for (int i = 0; i < 8; i++) {
            int row = (lt >> 3) + i * 8, col = lt & 7;
            CP_ASYNC16(dstb + row * 144 + col * 16,
                       s + (size_t)(b * SEQ + kt0 + row) * DM + h * DK + col * 8);
        }
    } else {
        const bf16* s = (tile == 3) ? g_Vtlo : g_Vthi;
        uint32_t dstb = stg + ((tile == 3) ? OVL : OVH);
        #pragma unroll
        for (int i = 0; i < 8; i++) {
            int row = (lt >> 3) + i * 8, col = lt & 7;
            CP_ASYNC16(dstb + row * 144 + col * 16,
                       s + (size_t)((h * BATCH + b) * DK + row) * SEQ + kt0 + col * 8);
        }
    }
}

__global__ void __launch_bounds__(256, 1)
attn_tc(const int* __restrict__ mask, float* __restrict__ scores_out) {
    extern __shared__ char smc[];
    const uint32_t sb = smem_u32(smc);
    const int tid = threadIdx.x, lane = tid & 31, w = tid >> 5;
    const int h = blockIdx.y, b = blockIdx.z;
    const int q0 = blockIdx.x * 128;
    const int g = lane >> 2, tg = lane & 3;

    // Q tiles (hi,lo) via cp.async
    {
        const int zt = tid >> 7, lt = tid & 127;
        const bf16* src = zt ? g_Qlo : g_Qhi;
        uint32_t dstb = sb + (zt ? SQL : SQH);
        #pragma unroll
        for (int i = 0; i < 8; i++) {
            int row = (lt >> 3) + i * 16, col = lt & 7;
            CP_ASYNC16(dstb + row * 144 + col * 16,
                       src + (size_t)(b * SEQ + q0 + row) * DM + h * DK + col * 8);
        }
    }
    issue_kv(sb + STAGE0, 0, h, b, tid);
    CP_COMMIT();

    uint32_t qh[4][4], ql[4][4];
    float O[8][4];
    #pragma unroll
    for (int nj = 0; nj < 8; nj++)
        #pragma unroll
        for (int e = 0; e < 4; e++) O[nj][e] = 0.f;
    float m0 = NEGINF, m1 = NEGINF, l0 = 0.f, l1 = 0.f;

    const int qr0 = q0 + w * 16 + g;

    for (int kt = 0; kt < 16; kt++) {
        if (kt + 1 < 16) {
            issue_kv(sb + STAGE0 + ((kt + 1) & 1) * STAGE_SZ, (kt + 1) * 64,
                     h, b, tid);
            CP_COMMIT();
            CP_WAIT(1);
        } else {
            CP_WAIT(0);
        }
        __syncthreads();

        if (kt == 0) {
            #pragma unroll
            for (int ks = 0; ks < 4; ks++) {
                uint32_t ra = sb + SQH + (uint32_t)(w * 16 + (lane & 15)) * 144
                            + ks * 32 + (lane >> 4) * 16;
                ldm_x4(qh[ks], ra);
                ldm_x4(ql[ks], ra + (SQL - SQH));
            }
        }

        const uint32_t stg = sb + STAGE0 + (kt & 1) * STAGE_SZ;
        float s[8][4];

        // ---- S = Q K^T (3-term split)
        #pragma unroll
        for (int njp = 0; njp < 4; njp++) {
            #pragma unroll
            for (int e = 0; e < 4; e++) { s[2*njp][e] = 0.f; s[2*njp+1][e] = 0.f; }
            #pragma unroll
            for (int ks = 0; ks < 4; ks++) {
                uint32_t kh4[4], kl4[4];
                uint32_t ad = stg + OKH
                    + (uint32_t)(njp * 16 + ((lane >> 4) & 1) * 8 + (lane & 7)) * 144
                    + ks * 32 + ((lane >> 3) & 1) * 16;
                ldm_x4(kh4, ad);
                ldm_x4(kl4, ad + (OKL - OKH));
                mma16816(s[2*njp],   qh[ks], kh4);
                mma16816(s[2*njp],   qh[ks], kl4);
                mma16816(s[2*njp],   ql[ks], kh4);
                mma16816(s[2*njp+1], qh[ks], kh4 + 2);
                mma16816(s[2*njp+1], qh[ks], kl4 + 2);
                mma16816(s[2*njp+1], ql[ks], kh4 + 2);
            }
        }

        // ---- mask + scale + write scores
        const int kt0 = kt * 64;
        const int* mb0 = mask + (size_t)(b * SEQ + qr0) * SEQ + kt0;
        const int* mb1 = mb0 + 8 * SEQ;
        float* so0 = scores_out + ((size_t)((h * BATCH + b) * SEQ + qr0)) * SEQ + kt0;
        float* so1 = so0 + 8 * SEQ;
        #pragma unroll
        for (int nj = 0; nj < 8; nj++) {
            int c = nj * 8 + tg * 2;
            int2 mv0 = *reinterpret_cast<const int2*>(mb0 + c);
            int2 mv1 = *reinterpret_cast<const int2*>(mb1 + c);
            s[nj][0] = mv0.x ? s[nj][0] * 0.125f : NEGINF;
            s[nj][1] = mv0.y ? s[nj][1] * 0.125f : NEGINF;
            s[nj][2] = mv1.x ? s[nj][2] * 0.125f : NEGINF;
            s[nj][3] = mv1.y ? s[nj][3] * 0.125f : NEGINF;
            *reinterpret_cast<float2*>(so0 + c) = make_float2(s[nj][0], s[nj][1]);
            *reinterpret_cast<float2*>(so1 + c) = make_float2(s[nj][2], s[nj][3]);
        }

        // ---- online softmax (rows fully warp-local; reduce over quad)
        float rm0 = NEGINF, rm1 = NEGINF;
        #pragma unroll
        for (int nj = 0; nj < 8; nj++) {
            rm0 = fmaxf(rm0, fmaxf(s[nj][0], s[nj][1]));
            rm1 = fmaxf(rm1, fmaxf(s[nj][2], s[nj][3]));
        }
        rm0 = fmaxf(rm0, __shfl_xor_sync(0xffffffffu, rm0, 1));
        rm0 = fmaxf(rm0, __shfl_xor_sync(0xffffffffu, rm0, 2));
        rm1 = fmaxf(rm1, __shfl_xor_sync(0xffffffffu, rm1, 1));
        rm1 = fmaxf(rm1, __shfl_xor_sync(0xffffffffu, rm1, 2));

        float mn0 = fmaxf(m0, rm0), mn1 = fmaxf(m1, rm1);
        float mu0 = fmaxf(mn0, -1e30f), mu1 = fmaxf(mn1, -1e30f);
        float c0 = __expf(fmaxf(m0, -1e30f) - mu0);
        float c1 = __expf(fmaxf(m1, -1e30f) - mu1);
        m0 = mn0; m1 = mn1;

        float rs0 = 0.f, rs1 = 0.f;
        #pragma unroll
        for (int nj = 0; nj < 8; nj++) {
            s[nj][0] = __expf(s[nj][0] - mu0);
            s[nj][1] = __expf(s[nj][1] - mu0);
            s[nj][2] = __expf(s[nj][2] - mu1);
            s[nj][3] = __expf(s[nj][3] - mu1);
            rs0 += s[nj][0] + s[nj][1];
            rs1 += s[nj][2] + s[nj][3];
        }
        rs0 += __shfl_xor_sync(0xffffffffu, rs0, 1);
        rs0 += __shfl_xor_sync(0xffffffffu, rs0, 2);
        rs1 += __shfl_xor_sync(0xffffffffu, rs1, 1);
        rs1 += __shfl_xor_sync(0xffffffffu, rs1, 2);
        l0 = l0 * c0 + rs0;
        l1 = l1 * c1 + rs1;

        #pragma unroll
        for (int nj = 0; nj < 8; nj++) {
            O[nj][0] *= c0; O[nj][1] *= c0;
            O[nj][2] *= c1; O[nj][3] *= c1;
        }

        // ---- pack P (C-frag -> A-frag identity), split hi/lo
        uint32_t ph[4][4], pl[4][4];
        #pragma unroll
        for (int ks = 0; ks < 4; ks++) {
            split_pack(s[2*ks][0],   s[2*ks][1],   ph[ks][0], pl[ks][0]);
            split_pack(s[2*ks][2],   s[2*ks][3],   ph[ks][1], pl[ks][1]);
            split_pack(s[2*ks+1][0], s[2*ks+1][1], ph[ks][2], pl[ks][2]);
            split_pack(s[2*ks+1][2], s[2*ks+1][3], ph[ks][3], pl[ks][3]);
        }

        // ---- O += P V (3-term split)
        #pragma unroll
        for (int ks = 0; ks < 4; ks++) {
            #pragma unroll
            for (int njp = 0; njp < 4; njp++) {
                uint32_t vh4[4], vl4[4];
                uint32_t ad = stg + OVH
                    + (uint32_t)(njp * 16 + ((lane >> 4) & 1) * 8 + (lane & 7)) * 144
                    + ks * 32 + ((lane >> 3) & 1) * 16;
                ldm_x4(vh4, ad);
                ldm_x4(vl4, ad + (OVL - OVH));
                mma16816(O[2*njp],   ph[ks], vh4);
                mma16816(O[2*njp],   ph[ks], vl4);
                mma16816(O[2*njp],   pl[ks], vh4);
                mma16816(O[2*njp+1], ph[ks], vh4 + 2);
                mma16816(O[2*njp+1], ph[ks], vl4 + 2);
                mma16816(O[2*njp+1], pl[ks], vh4 + 2);
            }
        }
        __syncthreads();
    }

    // ---- epilogue: O/l -> split-bf16 concat
    float inv0 = 1.f / l0, inv1 = 1.f / l1;
    uint16_t* ch = (uint16_t*)g_Chi;
    uint16_t* cl = (uint16_t*)g_Clo;
    size_t base0 = (size_t)(b * SEQ + qr0) * DM + h * DK;
    size_t base1 = base0 + (size_t)8 * DM;
    #pragma unroll
    for (int nj = 0; nj < 8; nj++) {
        int c = nj * 8 + tg * 2;
        uint32_t h0, l0v, h1, l1v;
        split_pack(O[nj][0] * inv0, O[nj][1] * inv0, h0, l0v);
        split_pack(O[nj][2] * inv1, O[nj][3] * inv1, h1, l1v);
        *reinterpret_cast<uint32_t*>(ch + base0 + c) = h0;
        *reinterpret_cast<uint32_t*>(cl + base0 + c) = l0v;
        *reinterpret_cast<uint32_t*>(ch + base1 + c) = h1;
        *reinterpret_cast<uint32_t*>(cl + base1 + c) = l1v;
    }
}

// ---------------------------------------------------------------------------
extern "C" void kernel_launch(void* const* d_in, const int* in_sizes, int n_in,
                              void* d_out, int out_size) {
    const float* q    = (const float*)d_in[0];
    const float* k    = (const float*)d_in[1];
    const float* v    = (const float*)d_in[2];
    const int*   mask = (const int*)  d_in[3];
    const float* Wq   = (const float*)d_in[4];
    const float* Wk   = (const float*)d_in[5];
    const float* Wv   = (const float*)d_in[6];
    const float* Wo   = (const float*)d_in[7];

    float* out    = (float*)d_out;
    float* scores = out + OUT_OFF;

    cudaFuncSetAttribute(gemm_mma,
                         cudaFuncAttributeMaxDynamicSharedMemorySize, GEMM_SMEM);
    cudaFuncSetAttribute(attn_tc,
                         cudaFuncAttributeMaxDynamicSharedMemorySize, ATTN_SMEM);

    split3_kernel<<<dim3(M_ROWS * DM / 256, 1, 3), 256>>>(q, k, v);
    prep_w_kernel<<<dim3(16, 16, 4), 256>>>(Wq, Wk, Wv, Wo);
    gemm_mma<<<dim3(DM / 128, M_ROWS / 128, 3), 256, GEMM_SMEM>>>(0, nullptr);
    vt_kernel<<<dim3(16, 64), 256>>>();
    attn_tc<<<dim3(SEQ / 128, H, BATCH), 256, ATTN_SMEM>>>(mask, scores);
    gemm_mma<<<dim3(DM / 128, M_ROWS / 128, 1), 256, GEMM_SMEM>>>(3, out);
}

// round 6
// speedup vs baseline: 2.2901x; 1.0919x over previous
#include <cuda_runtime.h>
#include <cuda_bf16.h>
#include <math.h>
#include <stdint.h>

#define H 16
#define BATCH 4
#define SEQ 1024
#define DM 1024
#define DK 64
#define M_ROWS (BATCH*SEQ)        // 4096
#define OUT_OFF (M_ROWS*DM)

using bf16 = __nv_bfloat16;

// ------------------------- device scratch (no allocs allowed) --------------
__device__ __align__(256) bf16  g_Ahi[3][M_ROWS*DM];   // split q,k,v inputs
__device__ __align__(256) bf16  g_Alo[3][M_ROWS*DM];
__device__ __align__(256) bf16  g_Whi[4][DM*DM];       // weights as B[n][k]
__device__ __align__(256) bf16  g_Wlo[4][DM*DM];
__device__ __align__(256) bf16  g_Qhi[M_ROWS*DM];      // [b,s][h*64+dk]
__device__ __align__(256) bf16  g_Qlo[M_ROWS*DM];
__device__ __align__(256) bf16  g_Khi[M_ROWS*DM];
__device__ __align__(256) bf16  g_Klo[M_ROWS*DM];
__device__ __align__(256) bf16  g_Vhi[M_ROWS*DM];
__device__ __align__(256) bf16  g_Vlo[M_ROWS*DM];
__device__ __align__(256) bf16  g_Vthi[H*BATCH*DK*SEQ]; // [h][b][dk][s]
__device__ __align__(256) bf16  g_Vtlo[H*BATCH*DK*SEQ];
__device__ __align__(256) bf16  g_Chi[M_ROWS*DM];      // attn concat out
__device__ __align__(256) bf16  g_Clo[M_ROWS*DM];
__device__ __align__(256) uint32_t g_maskbits[M_ROWS*32]; // [b,q][32 words]

// ------------------------- PTX helpers (base-target legal) ------------------
__device__ __forceinline__ uint32_t smem_u32(const void* p) {
    uint32_t a;
    asm("{ .reg .u64 t; cvta.to.shared.u64 t, %1; cvt.u32.u64 %0, t; }"
        : "=r"(a) : "l"(p));
    return a;
}
#define CP_ASYNC16(s, g) \
    asm volatile("cp.async.cg.shared.global [%0], [%1], 16;" :: "r"(s), "l"(g))
#define CP_COMMIT() asm volatile("cp.async.commit_group;" ::: "memory")
#define CP_WAIT(n)  asm volatile("cp.async.wait_group %0;" :: "n"(n) : "memory")

__device__ __forceinline__ void ldm_x4(uint32_t* r, uint32_t addr) {
    asm volatile("ldmatrix.sync.aligned.m8n8.x4.shared.b16 {%0,%1,%2,%3}, [%4];"
        : "=r"(r[0]), "=r"(r[1]), "=r"(r[2]), "=r"(r[3]) : "r"(addr));
}
__device__ __forceinline__ void ldm_x2(uint32_t* r, uint32_t addr) {
    asm volatile("ldmatrix.sync.aligned.m8n8.x2.shared.b16 {%0,%1}, [%2];"
        : "=r"(r[0]), "=r"(r[1]) : "r"(addr));
}
__device__ __forceinline__ void mma16816(float* c, const uint32_t* a,
                                         const uint32_t* b) {
    asm volatile("mma.sync.aligned.m16n8k16.row.col.f32.bf16.bf16.f32 "
        "{%0,%1,%2,%3}, {%4,%5,%6,%7}, {%8,%9}, {%0,%1,%2,%3};"
        : "+f"(c[0]), "+f"(c[1]), "+f"(c[2]), "+f"(c[3])
        : "r"(a[0]), "r"(a[1]), "r"(a[2]), "r"(a[3]), "r"(b[0]), "r"(b[1]));
}
__device__ __forceinline__ void split_pack(float a, float b,
                                           uint32_t& hi, uint32_t& lo) {
    __nv_bfloat162 h2 = __floats2bfloat162_rn(a, b);
    float ra = a - __bfloat162float(h2.x);
    float rb = b - __bfloat162float(h2.y);
    __nv_bfloat162 l2 = __floats2bfloat162_rn(ra, rb);
    hi = *reinterpret_cast<uint32_t*>(&h2);
    lo = *reinterpret_cast<uint32_t*>(&l2);
}

// ---------------------------------------------------------------------------
// Prep: fp32 -> bf16 hi/lo split for q,k,v inputs (float4 vectorized)
// ---------------------------------------------------------------------------
__global__ void split3_kernel(const float* __restrict__ a,
                              const float* __restrict__ b,
                              const float* __restrict__ c) {
    int z = blockIdx.z;
    const float* x = (z == 0) ? a : (z == 1) ? b : c;
    int i = (blockIdx.x * 256 + threadIdx.x) * 4;
    float4 v = *reinterpret_cast<const float4*>(x + i);
    uint32_t h0, l0, h1, l1;
    split_pack(v.x, v.y, h0, l0);
    split_pack(v.z, v.w, h1, l1);
    *reinterpret_cast<uint2*>((uint16_t*)g_Ahi[z] + i) = make_uint2(h0, h1);
    *reinterpret_cast<uint2*>((uint16_t*)g_Alo[z] + i) = make_uint2(l0, l1);
}

// ---------------------------------------------------------------------------
// Prep: mask int32 [B,S,S] -> bit pack [b,q][32 words].  warp-ballot.
// block 256 (8 warps), each warp packs one row. grid 512.
// ---------------------------------------------------------------------------
__global__ void maskpack_kernel(const int* __restrict__ mask) {
    int row = blockIdx.x * 8 + (threadIdx.x >> 5);
    int lane = threadIdx.x & 31;
    const int* r = mask + (size_t)row * SEQ;
    uint32_t myword = 0;
    #pragma unroll
    for (int w = 0; w < 32; w++) {
        int v = r[w * 32 + lane];
        uint32_t bits = __ballot_sync(0xffffffffu, v != 0);
        if (lane == w) myword = bits;
    }
    g_maskbits[(size_t)row * 32 + lane] = myword;
}

// ---------------------------------------------------------------------------
// Prep: weights -> B[n][k] bf16 hi/lo, smem-transposed.
// ---------------------------------------------------------------------------
__global__ void prep_w_kernel(const float* __restrict__ Wq,
                              const float* __restrict__ Wk,
                              const float* __restrict__ Wv,
                              const float* __restrict__ Wo) {
    __shared__ float ws[64][65];
    const int z = blockIdx.z;
    const float* W = (z == 0) ? Wq : (z == 1) ? Wk : (z == 2) ? Wv : Wo;
    const int t = threadIdx.x;
    const int k0 = blockIdx.x * 64;
    const int nb = blockIdx.y;

    #pragma unroll
    for (int i = 0; i < 4; i++) {
        int id = t + i * 256;
        int row = id >> 4, c4 = id & 15;
        const float* src = (z < 3)
            ? W + (size_t)nb * 65536 + (size_t)(k0 + row) * 64 + c4 * 4
            : W + (size_t)(k0 + row) * DM + nb * 64 + c4 * 4;
        float4 v = *reinterpret_cast<const float4*>(src);
        ws[row][c4 * 4 + 0] = v.x; ws[row][c4 * 4 + 1] = v.y;
        ws[row][c4 * 4 + 2] = v.z; ws[row][c4 * 4 + 3] = v.w;
    }
    __syncthreads();

    const int kk = t >> 2, kg = t & 3;
    uint32_t hi[8], lo[8];
    #pragma unroll
    for (int j = 0; j < 8; j++)
        split_pack(ws[kg * 16 + 2 * j][kk], ws[kg * 16 + 2 * j + 1][kk],
                   hi[j], lo[j]);
    size_t off = (size_t)(nb * 64 + kk) * DM + k0 + kg * 16;
    uint16_t* dh = (uint16_t*)g_Whi[z];
    uint16_t* dl = (uint16_t*)g_Wlo[z];
    *reinterpret_cast<uint4*>(dh + off)     = make_uint4(hi[0], hi[1], hi[2], hi[3]);
    *reinterpret_cast<uint4*>(dh + off + 8) = make_uint4(hi[4], hi[5], hi[6], hi[7]);
    *reinterpret_cast<uint4*>(dl + off)     = make_uint4(lo[0], lo[1], lo[2], lo[3]);
    *reinterpret_cast<uint4*>(dl + off + 8) = make_uint4(lo[4], lo[5], lo[6], lo[7]);
}

// ---------------------------------------------------------------------------
// Prep: V [b,s][h*64+dk] bf16 hi/lo -> Vt [h][b][dk][s].  grid (16, 64)
// ---------------------------------------------------------------------------
__global__ void vt_kernel() {
    __shared__ uint16_t tile[2][64][72];
    const int t = threadIdx.x;
    const int h = blockIdx.y >> 2, b = blockIdx.y & 3, s0 = blockIdx.x * 64;

    #pragma unroll
    for (int i = 0; i < 4; i++) {
        int id = t + i * 256;
        int z = id >> 9, rid = id & 511;
        int row = rid >> 3, c8 = rid & 7;
        const uint16_t* src = (const uint16_t*)(z ? g_Vlo : g_Vhi);
        uint4 v = *reinterpret_cast<const uint4*>(
            src + (size_t)(b * SEQ + s0 + row) * DM + h * DK + c8 * 8);
        *reinterpret_cast<uint4*>(&tile[z][row][c8 * 8]) = v;
    }
    __syncthreads();
    #pragma unroll
    for (int i = 0; i < 4; i++) {
        int id = t + i * 256;
        int z = id >> 9, rid = id & 511;
        int dk = rid >> 3, sc = rid & 7;
        uint32_t u[4];
        #pragma unroll
        for (int j = 0; j < 4; j++) {
            uint32_t a = tile[z][sc * 8 + 2 * j][dk];
            uint32_t c = tile[z][sc * 8 + 2 * j + 1][dk];
            u[j] = a | (c << 16);
        }
        uint16_t* dst = (uint16_t*)(z ? g_Vtlo : g_Vthi);
        *reinterpret_cast<uint4*>(
            dst + (size_t)((h * BATCH + b) * DK + dk) * SEQ + s0 + sc * 8) =
            make_uint4(u[0], u[1], u[2], u[3]);
    }
}

// ---------------------------------------------------------------------------
// mma.sync split-bf16 GEMM, 3-stage cp.async pipeline, 1 barrier/iter.
// ---------------------------------------------------------------------------
#define BK 32
#define NKC (DM / BK)
#define TILE_B  (128 * 80)
#define STAGE_B (4 * TILE_B)
#define GEMM_SMEM (3 * STAGE_B)   // 122880

__device__ __forceinline__ void gemm_issue(uint32_t tb, const bf16* lsrc,
                                           int lr0, int lt, int k0) {
    #pragma unroll
    for (int c = 0; c < 8; c++) {
        int ch = lt + c * 64;
        int row = ch >> 2, kc = ch & 3;
        CP_ASYNC16(tb + row * 80 + kc * 16,
                   lsrc + (size_t)(lr0 + row) * DM + k0 + kc * 8);
    }
}

__global__ void __launch_bounds__(256, 1)
gemm_mma(int base_sel, float* __restrict__ out_ptr) {
    extern __shared__ char smem[];
    const int sel = base_sel + blockIdx.z;

    const bf16* Ah; const bf16* Al;
    bf16* Oh = nullptr; bf16* Ol = nullptr;
    if (sel == 0)      { Ah = g_Ahi[0]; Al = g_Alo[0]; Oh = g_Qhi; Ol = g_Qlo; }
    else if (sel == 1) { Ah = g_Ahi[1]; Al = g_Alo[1]; Oh = g_Khi; Ol = g_Klo; }
    else if (sel == 2) { Ah = g_Ahi[2]; Al = g_Alo[2]; Oh = g_Vhi; Ol = g_Vlo; }
    else               { Ah = g_Chi;    Al = g_Clo; }
    const bf16* Bh = g_Whi[sel];
    const bf16* Bl = g_Wlo[sel];

    const uint32_t sb = smem_u32(smem);
    const int tid = threadIdx.x;
    const int wid = tid >> 5, lane = tid & 31;
    const int m0 = blockIdx.y * 128, n0 = blockIdx.x * 128;
    const int wm = (wid & 1) * 64;
    const int wn = (wid >> 1) * 32;

    const int lt_tile = tid >> 6;
    const int lt = tid & 63;
    const bf16* lsrc = (lt_tile == 0) ? Ah : (lt_tile == 1) ? Al
                     : (lt_tile == 2) ? Bh : Bl;
    const int lr0 = (lt_tile >= 2) ? n0 : m0;
    const uint32_t ltb = sb + lt_tile * TILE_B;

    float acc[4][4][4];
    #pragma unroll
    for (int i = 0; i < 4; i++)
        #pragma unroll
        for (int j = 0; j < 4; j++)
            #pragma unroll
            for (int e = 0; e < 4; e++) acc[i][j][e] = 0.f;

    gemm_issue(ltb, lsrc, lr0, lt, 0);          CP_COMMIT();
    gemm_issue(ltb + STAGE_B, lsrc, lr0, lt, BK); CP_COMMIT();

    int sidx = 0;
    for (int kch = 0; kch < NKC; kch++) {
        if (kch + 1 < NKC) { CP_WAIT(1); } else { CP_WAIT(0); }
        __syncthreads();
        if (kch + 2 < NKC) {
            int si2 = sidx + 2; if (si2 >= 3) si2 -= 3;
            gemm_issue(ltb + si2 * STAGE_B, lsrc, lr0, lt, (kch + 2) * BK);
            CP_COMMIT();
        }

        const uint32_t stage = sb + sidx * STAGE_B;
        const uint32_t sAh = stage;
        const uint32_t sAl = stage + TILE_B;
        const uint32_t sBh = stage + 2 * TILE_B;
        const uint32_t sBl = stage + 3 * TILE_B;

        #pragma unroll
        for (int ks = 0; ks < 2; ks++) {
            uint32_t ah[4][4], al[4][4], bh[4][2], bl[4][2];
            #pragma unroll
            for (int mi = 0; mi < 4; mi++) {
                uint32_t ra = (uint32_t)(wm + mi * 16 + (lane & 15)) * 80
                            + ks * 32 + (lane >> 4) * 16;
                ldm_x4(ah[mi], sAh + ra);
                ldm_x4(al[mi], sAl + ra);
            }
            #pragma unroll
            for (int nj = 0; nj < 4; nj++) {
                uint32_t rb = (uint32_t)(wn + nj * 8 + (lane & 7)) * 80
                            + ks * 32 + ((lane >> 3) & 1) * 16;
                ldm_x2(bh[nj], sBh + rb);
                ldm_x2(bl[nj], sBl + rb);
            }
            #pragma unroll
            for (int mi = 0; mi < 4; mi++)
                #pragma unroll
                for (int nj = 0; nj < 4; nj++) {
                    mma16816(acc[mi][nj], ah[mi], bh[nj]);
                    mma16816(acc[mi][nj], ah[mi], bl[nj]);
                    mma16816(acc[mi][nj], al[mi], bh[nj]);
                }
        }
        sidx++; if (sidx == 3) sidx = 0;
    }

    if (sel < 3) {
        uint16_t* oh = (uint16_t*)Oh;
        uint16_t* ol = (uint16_t*)Ol;
        #pragma unroll
        for (int mi = 0; mi < 4; mi++) {
            int row = m0 + wm + mi * 16 + (lane >> 2);
            #pragma unroll
            for (int nj = 0; nj < 4; nj++) {
                int col = n0 + wn + nj * 8 + (lane & 3) * 2;
                uint32_t h0, l0v, h1, l1v;
                split_pack(acc[mi][nj][0], acc[mi][nj][1], h0, l0v);
                split_pack(acc[mi][nj][2], acc[mi][nj][3], h1, l1v);
                *reinterpret_cast<uint32_t*>(oh + (size_t)row * DM + col) = h0;
                *reinterpret_cast<uint32_t*>(ol + (size_t)row * DM + col) = l0v;
                *reinterpret_cast<uint32_t*>(oh + (size_t)(row + 8) * DM + col) = h1;
                *reinterpret_cast<uint32_t*>(ol + (size_t)(row + 8) * DM + col) = l1v;
            }
        }
    } else {
        #pragma unroll
        for (int mi = 0; mi < 4; mi++) {
            int row = m0 + wm + mi * 16 + (lane >> 2);
            #pragma unroll
            for (int nj = 0; nj < 4; nj++) {
                int col = n0 + wn + nj * 8 + (lane & 3) * 2;
                *reinterpret_cast<float2*>(out_ptr + (size_t)row * DM + col) =
                    make_float2(acc[mi][nj][0], acc[mi][nj][1]);
                *reinterpret_cast<float2*>(out_ptr + (size_t)(row + 8) * DM + col) =
                    make_float2(acc[mi][nj][2], acc[mi][nj][3]);
            }
        }
    }
}

// ---------------------------------------------------------------------------
// Tensor-core fused attention, 3-stage KV pipeline, bit-packed mask.
// grid (8, 16, 4), block 256 (8 warps x 16 rows).
// ---------------------------------------------------------------------------
#define SQH 0
#define SQL 18432
#define STAGE0 36864
#define STAGE_SZ 36864
#define OKH 0
#define OKL 9216
#define OVH 18432
#define OVL 27648
#define ATTN_SMEM (36864 + 3 * 36864)   // 147456
#define NEGINF (-INFINITY)

__device__ __forceinline__ void issue_kv(uint32_t stg, int kt0, int h, int b,
                                         int tid) {
    const int tile = tid >> 6, lt = tid & 63;
    if (tile < 2) {
        const bf16* s = tile ? g_Klo : g_Khi;
        uint32_t dstb = stg + (tile ? OKL : OKH);
        #pragma unroll
        for (int i = 0; i < 8; i++) {
            int row = (lt >> 3) + i * 8, col = lt & 7;
            CP_ASYNC16(dstb + row * 144 + col * 16,
                       s + (size_t)(b * SEQ + kt0 + row) * DM + h * DK + col * 8);
        }
    } else {
        const bf16* s = (tile == 3) ? g_Vtlo : g_Vthi;
        uint32_t dstb = stg + ((tile == 3) ? OVL : OVH);
        #pragma unroll
        for (int i = 0; i < 8; i++) {
            int row = (lt >> 3) + i * 8, col = lt & 7;
            CP_ASYNC16(dstb + row * 144 + col * 16,
                       s + (size_t)((h * BATCH + b) * DK + row) * SEQ + kt0 + col * 8);
        }
    }
}

__global__ void __launch_bounds__(256, 1)
attn_tc(float* __restrict__ scores_out) {
    extern __shared__ char smc[];
    const uint32_t sb = smem_u32(smc);
    const int tid = threadIdx.x, lane = tid & 31, w = tid >> 5;
    const int h = blockIdx.y, b = blockIdx.z;
    const int q0 = blockIdx.x * 128;
    const int g = lane >> 2, tg = lane & 3;

    // Q tiles (hi,lo) via cp.async, grouped with KV stage 0
    {
        const int zt = tid >> 7, lt = tid & 127;
        const bf16* src = zt ? g_Qlo : g_Qhi;
        uint32_t dstb = sb + (zt ? SQL : SQH);
        #pragma unroll
        for (int i = 0; i < 8; i++) {
            int row = (lt >> 3) + i * 16, col = lt & 7;
            CP_ASYNC16(dstb + row * 144 + col * 16,
                       src + (size_t)(b * SEQ + q0 + row) * DM + h * DK + col * 8);
        }
    }
    issue_kv(sb + STAGE0, 0, h, b, tid);
    CP_COMMIT();
    issue_kv(sb + STAGE0 + STAGE_SZ, 64, h, b, tid);
    CP_COMMIT();

    uint32_t qh[4][4], ql[4][4];
    float O[8][4];
    #pragma unroll
    for (int nj = 0; nj < 8; nj++)
        #pragma unroll
        for (int e = 0; e < 4; e++) O[nj][e] = 0.f;
    float m0 = NEGINF, m1 = NEGINF, l0 = 0.f, l1 = 0.f;

    const int qr0 = q0 + w * 16 + g;
    const uint32_t* mrow = g_maskbits + ((size_t)(b * SEQ + qr0)) * 32;

    int sidx = 0;
    for (int kt = 0; kt < 16; kt++) {
        if (kt + 1 < 16) { CP_WAIT(1); } else { CP_WAIT(0); }
        __syncthreads();
        if (kt + 2 < 16) {
            int si2 = sidx + 2; if (si2 >= 3) si2 -= 3;
            issue_kv(sb + STAGE0 + si2 * STAGE_SZ, (kt + 2) * 64, h, b, tid);
            CP_COMMIT();
        }

        if (kt == 0) {
            #pragma unroll
            for (int ks = 0; ks < 4; ks++) {
                uint32_t ra = sb + SQH + (uint32_t)(w * 16 + (lane & 15)) * 144
                            + ks * 32 + (lane >> 4) * 16;
                ldm_x4(qh[ks], ra);
                ldm_x4(ql[ks], ra + (SQL - SQH));
            }
        }

        const uint32_t stg = sb + STAGE0 + sidx * STAGE_SZ;
        float s[8][4];

        // ---- S = Q K^T (3-term split)
        #pragma unroll
        for (int njp = 0; njp < 4; njp++) {
            #pragma unroll
            for (int e = 0; e < 4; e++) { s[2*njp][e] = 0.f; s[2*njp+1][e] = 0.f; }
            #pragma unroll
            for (int ks = 0; ks < 4; ks++) {
                uint32_t kh4[4], kl4[4];
                uint32_t ad = stg + OKH
                    + (uint32_t)(njp * 16 + ((lane >> 4) & 1) * 8 + (lane & 7)) * 144
                    + ks * 32 + ((lane >> 3) & 1) * 16;
                ldm_x4(kh4, ad);
                ldm_x4(kl4, ad + (OKL - OKH));
                mma16816(s[2*njp],   qh[ks], kh4);
                mma16816(s[2*njp],   qh[ks], kl4);
                mma16816(s[2*njp],   ql[ks], kh4);
                mma16816(s[2*njp+1], qh[ks], kh4 + 2);
                mma16816(s[2*njp+1], qh[ks], kl4 + 2);
                mma16816(s[2*njp+1], ql[ks], kh4 + 2);
            }
        }

        // ---- mask (bit-packed) + scale + write scores
        const int kt0 = kt * 64;
        const uint32_t w0a = mrow[kt * 2],       w0b = mrow[kt * 2 + 1];
        const uint32_t w1a = mrow[256 + kt * 2], w1b = mrow[256 + kt * 2 + 1];
        float* so0 = scores_out + ((size_t)((h * BATCH + b) * SEQ + qr0)) * SEQ + kt0;
        float* so1 = so0 + 8 * SEQ;
        #pragma unroll
        for (int nj = 0; nj < 8; nj++) {
            int c = nj * 8 + tg * 2;
            uint32_t wr0 = (nj < 4) ? w0a : w0b;
            uint32_t wr1 = (nj < 4) ? w1a : w1b;
            int sh = c & 31;
            s[nj][0] = ((wr0 >> sh) & 1)       ? s[nj][0] * 0.125f : NEGINF;
            s[nj][1] = ((wr0 >> (sh + 1)) & 1) ? s[nj][1] * 0.125f : NEGINF;
            s[nj][2] = ((wr1 >> sh) & 1)       ? s[nj][2] * 0.125f : NEGINF;
            s[nj][3] = ((wr1 >> (sh + 1)) & 1) ? s[nj][3] * 0.125f : NEGINF;
            *reinterpret_cast<float2*>(so0 + c) = make_float2(s[nj][0], s[nj][1]);
            *reinterpret_cast<float2*>(so1 + c) = make_float2(s[nj][2], s[nj][3]);
        }

        // ---- online softmax (rows fully warp-local; reduce over quad)
        float rm0 = NEGINF, rm1 = NEGINF;
        #pragma unroll
        for (int nj = 0; nj < 8; nj++) {
            rm0 = fmaxf(rm0, fmaxf(s[nj][0], s[nj][1]));
            rm1 = fmaxf(rm1, fmaxf(s[nj][2], s[nj][3]));
        }
        rm0 = fmaxf(rm0, __shfl_xor_sync(0xffffffffu, rm0, 1));
        rm0 = fmaxf(rm0, __shfl_xor_sync(0xffffffffu, rm0, 2));
        rm1 = fmaxf(rm1, __shfl_xor_sync(0xffffffffu, rm1, 1));
        rm1 = fmaxf(rm1, __shfl_xor_sync(0xffffffffu, rm1, 2));

        float mn0 = fmaxf(m0, rm0), mn1 = fmaxf(m1, rm1);
        float mu0 = fmaxf(mn0, -1e30f), mu1 = fmaxf(mn1, -1e30f);
        float c0 = __expf(fmaxf(m0, -1e30f) - mu0);
        float c1 = __expf(fmaxf(m1, -1e30f) - mu1);
        m0 = mn0; m1 = mn1;

        float rs0 = 0.f, rs1 = 0.f;
        #pragma unroll
        for (int nj = 0; nj < 8; nj++) {
            s[nj][0] = __expf(s[nj][0] - mu0);
            s[nj][1] = __expf(s[nj][1] - mu0);
            s[nj][2] = __expf(s[nj][2] - mu1);
            s[nj][3] = __expf(s[nj][3] - mu1);
            rs0 += s[nj][0] + s[nj][1];
            rs1 += s[nj][2] + s[nj][3];
        }
        rs0 += __shfl_xor_sync(0xffffffffu, rs0, 1);
        rs0 += __shfl_xor_sync(0xffffffffu, rs0, 2);
        rs1 += __shfl_xor_sync(0xffffffffu, rs1, 1);
        rs1 += __shfl_xor_sync(0xffffffffu, rs1, 2);
        l0 = l0 * c0 + rs0;
        l1 = l1 * c1 + rs1;

        #pragma unroll
        for (int nj = 0; nj < 8; nj++) {
            O[nj][0] *= c0; O[nj][1] *= c0;
            O[nj][2] *= c1; O[nj][3] *= c1;
        }

        // ---- pack P (C-frag -> A-frag identity), split hi/lo
        uint32_t ph[4][4], pl[4][4];
        #pragma unroll
        for (int ks = 0; ks < 4; ks++) {
            split_pack(s[2*ks][0],   s[2*ks][1],   ph[ks][0], pl[ks][0]);
            split_pack(s[2*ks][2],   s[2*ks][3],   ph[ks][1], pl[ks][1]);
            split_pack(s[2*ks+1][0], s[2*ks+1][1], ph[ks][2], pl[ks][2]);
            split_pack(s[2*ks+1][2], s[2*ks+1][3], ph[ks][3], pl[ks][3]);
        }

        // ---- O += P V (3-term split)
        #pragma unroll
        for (int ks = 0; ks < 4; ks++) {
            #pragma unroll
            for (int njp = 0; njp < 4; njp++) {
                uint32_t vh4[4], vl4[4];
                uint32_t ad = stg + OVH
                    + (uint32_t)(njp * 16 + ((lane >> 4) & 1) * 8 + (lane & 7)) * 144
                    + ks * 32 + ((lane >> 3) & 1) * 16;
                ldm_x4(vh4, ad);
                ldm_x4(vl4, ad + (OVL - OVH));
                mma16816(O[2*njp],   ph[ks], vh4);
                mma16816(O[2*njp],   ph[ks], vl4);
                mma16816(O[2*njp],   pl[ks], vh4);
                mma16816(O[2*njp+1], ph[ks], vh4 + 2);
                mma16816(O[2*njp+1], ph[ks], vl4 + 2);
                mma16816(O[2*njp+1], pl[ks], vh4 + 2);
            }
        }
        sidx++; if (sidx == 3) sidx = 0;
    }

    // ---- epilogue: O/l -> split-bf16 concat
    float inv0 = 1.f / l0, inv1 = 1.f / l1;
    uint16_t* ch = (uint16_t*)g_Chi;
    uint16_t* cl = (uint16_t*)g_Clo;
    size_t base0 = (size_t)(b * SEQ + qr0) * DM + h * DK;
    size_t base1 = base0 + (size_t)8 * DM;
    #pragma unroll
    for (int nj = 0; nj < 8; nj++) {
        int c = nj * 8 + tg * 2;
        uint32_t h0, l0v, h1, l1v;
        split_pack(O[nj][0] * inv0, O[nj][1] * inv0, h0, l0v);
        split_pack(O[nj][2] * inv1, O[nj][3] * inv1, h1, l1v);
        *reinterpret_cast<uint32_t*>(ch + base0 + c) = h0;
        *reinterpret_cast<uint32_t*>(cl + base0 + c) = l0v;
        *reinterpret_cast<uint32_t*>(ch + base1 + c) = h1;
        *reinterpret_cast<uint32_t*>(cl + base1 + c) = l1v;
    }
}

// ---------------------------------------------------------------------------
extern "C" void kernel_launch(void* const* d_in, const int* in_sizes, int n_in,
                              void* d_out, int out_size) {
    const float* q    = (const float*)d_in[0];
    const float* k    = (const float*)d_in[1];
    const float* v    = (const float*)d_in[2];
    const int*   mask = (const int*)  d_in[3];
    const float* Wq   = (const float*)d_in[4];
    const float* Wk   = (const float*)d_in[5];
    const float* Wv   = (const float*)d_in[6];
    const float* Wo   = (const float*)d_in[7];

    float* out    = (float*)d_out;
    float* scores = out + OUT_OFF;

    cudaFuncSetAttribute(gemm_mma,
                         cudaFuncAttributeMaxDynamicSharedMemorySize, GEMM_SMEM);
    cudaFuncSetAttribute(attn_tc,
                         cudaFuncAttributeMaxDynamicSharedMemorySize, ATTN_SMEM);

    maskpack_kernel<<<M_ROWS / 8, 256>>>(mask);
    split3_kernel<<<dim3(M_ROWS * DM / 1024, 1, 3), 256>>>(q, k, v);
    prep_w_kernel<<<dim3(16, 16, 4), 256>>>(Wq, Wk, Wv, Wo);
    gemm_mma<<<dim3(DM / 128, M_ROWS / 128, 3), 256, GEMM_SMEM>>>(0, nullptr);
    vt_kernel<<<dim3(16, 64), 256>>>();
    attn_tc<<<dim3(SEQ / 128, H, BATCH), 256, ATTN_SMEM>>>(scores);
    gemm_mma<<<dim3(DM / 128, M_ROWS / 128, 1), 256, GEMM_SMEM>>>(3, out);
}

// round 10
// speedup vs baseline: 2.5189x; 1.0999x over previous
#include <cuda_runtime.h>
#include <cuda_bf16.h>
#include <math.h>
#include <stdint.h>

#define H 16
#define BATCH 4
#define SEQ 1024
#define DM 1024
#define DK 64
#define M_ROWS (BATCH*SEQ)        // 4096
#define OUT_OFF (M_ROWS*DM)

using bf16 = __nv_bfloat16;

// ------------------------- device scratch (no allocs allowed) --------------
__device__ __align__(256) bf16  g_Ahi[3][M_ROWS*DM];   // split q,k,v inputs
__device__ __align__(256) bf16  g_Alo[3][M_ROWS*DM];
__device__ __align__(256) bf16  g_Whi[4][DM*DM];       // weights as B[n][k]
__device__ __align__(256) bf16  g_Wlo[4][DM*DM];
__device__ __align__(256) bf16  g_Qhi[M_ROWS*DM];      // [b,s][h*64+dk]
__device__ __align__(256) bf16  g_Qlo[M_ROWS*DM];
__device__ __align__(256) bf16  g_Khi[M_ROWS*DM];
__device__ __align__(256) bf16  g_Klo[M_ROWS*DM];
__device__ __align__(256) bf16  g_Vhi[M_ROWS*DM];
__device__ __align__(256) bf16  g_Vlo[M_ROWS*DM];
__device__ __align__(256) bf16  g_Vthi[H*BATCH*DK*SEQ]; // [h][b][dk][s]
__device__ __align__(256) bf16  g_Vtlo[H*BATCH*DK*SEQ];
__device__ __align__(256) bf16  g_Chi[M_ROWS*DM];      // attn concat out
__device__ __align__(256) bf16  g_Clo[M_ROWS*DM];
__device__ __align__(256) uint32_t g_maskbits[M_ROWS*32]; // [b,q][32 words]

// ------------------------- PTX helpers (base-target legal) ------------------
__device__ __forceinline__ uint32_t smem_u32(const void* p) {
    uint32_t a;
    asm("{ .reg .u64 t; cvta.to.shared.u64 t, %1; cvt.u32.u64 %0, t; }"
        : "=r"(a) : "l"(p));
    return a;
}
#define CP_ASYNC16(s, g) \
    asm volatile("cp.async.cg.shared.global [%0], [%1], 16;" :: "r"(s), "l"(g))
#define CP_COMMIT() asm volatile("cp.async.commit_group;" ::: "memory")
#define CP_WAIT(n)  asm volatile("cp.async.wait_group %0;" :: "n"(n) : "memory")

__device__ __forceinline__ void ldm_x4(uint32_t* r, uint32_t addr) {
    asm volatile("ldmatrix.sync.aligned.m8n8.x4.shared.b16 {%0,%1,%2,%3}, [%4];"
        : "=r"(r[0]), "=r"(r[1]), "=r"(r[2]), "=r"(r[3]) : "r"(addr));
}
__device__ __forceinline__ void ldm_x2(uint32_t* r, uint32_t addr) {
    asm volatile("ldmatrix.sync.aligned.m8n8.x2.shared.b16 {%0,%1}, [%2];"
        : "=r"(r[0]), "=r"(r[1]) : "r"(addr));
}
__device__ __forceinline__ void mma16816(float* c, const uint32_t* a,
                                         const uint32_t* b) {
    asm volatile("mma.sync.aligned.m16n8k16.row.col.f32.bf16.bf16.f32 "
        "{%0,%1,%2,%3}, {%4,%5,%6,%7}, {%8,%9}, {%0,%1,%2,%3};"
        : "+f"(c[0]), "+f"(c[1]), "+f"(c[2]), "+f"(c[3])
        : "r"(a[0]), "r"(a[1]), "r"(a[2]), "r"(a[3]), "r"(b[0]), "r"(b[1]));
}
__device__ __forceinline__ void split_pack(float a, float b,
                                           uint32_t& hi, uint32_t& lo) {
    __nv_bfloat162 h2 = __floats2bfloat162_rn(a, b);
    float ra = a - __bfloat162float(h2.x);
    float rb = b - __bfloat162float(h2.y);
    __nv_bfloat162 l2 = __floats2bfloat162_rn(ra, rb);
    hi = *reinterpret_cast<uint32_t*>(&h2);
    lo = *reinterpret_cast<uint32_t*>(&l2);
}

// ---------------------------------------------------------------------------
// Prep kernels
// ---------------------------------------------------------------------------
__global__ void split3_kernel(const float* __restrict__ a,
                              const float* __restrict__ b,
                              const float* __restrict__ c) {
    int z = blockIdx.z;
    const float* x = (z == 0) ? a : (z == 1) ? b : c;
    int i = (blockIdx.x * 256 + threadIdx.x) * 4;
    float4 v = *reinterpret_cast<const float4*>(x + i);
    uint32_t h0, l0, h1, l1;
    split_pack(v.x, v.y, h0, l0);
    split_pack(v.z, v.w, h1, l1);
    *reinterpret_cast<uint2*>((uint16_t*)g_Ahi[z] + i) = make_uint2(h0, h1);
    *reinterpret_cast<uint2*>((uint16_t*)g_Alo[z] + i) = make_uint2(l0, l1);
}

__global__ void maskpack_kernel(const int* __restrict__ mask) {
    int row = blockIdx.x * 8 + (threadIdx.x >> 5);
    int lane = threadIdx.x & 31;
    const int* r = mask + (size_t)row * SEQ;
    uint32_t myword = 0;
    #pragma unroll
    for (int w = 0; w < 32; w++) {
        int v = r[w * 32 + lane];
        uint32_t bits = __ballot_sync(0xffffffffu, v != 0);
        if (lane == w) myword = bits;
    }
    g_maskbits[(size_t)row * 32 + lane] = myword;
}

__global__ void prep_w_kernel(const float* __restrict__ Wq,
                              const float* __restrict__ Wk,
                              const float* __restrict__ Wv,
                              const float* __restrict__ Wo) {
    __shared__ float ws[64][65];
    const int z = blockIdx.z;
    const float* W = (z == 0) ? Wq : (z == 1) ? Wk : (z == 2) ? Wv : Wo;
    const int t = threadIdx.x;
    const int k0 = blockIdx.x * 64;
    const int nb = blockIdx.y;

    #pragma unroll
    for (int i = 0; i < 4; i++) {
        int id = t + i * 256;
        int row = id >> 4, c4 = id & 15;
        const float* src = (z < 3)
            ? W + (size_t)nb * 65536 + (size_t)(k0 + row) * 64 + c4 * 4
            : W + (size_t)(k0 + row) * DM + nb * 64 + c4 * 4;
        float4 v = *reinterpret_cast<const float4*>(src);
        ws[row][c4 * 4 + 0] = v.x; ws[row][c4 * 4 + 1] = v.y;
        ws[row][c4 * 4 + 2] = v.z; ws[row][c4 * 4 + 3] = v.w;
    }
    __syncthreads();

    const int kk = t >> 2, kg = t & 3;
    uint32_t hi[8], lo[8];
    #pragma unroll
    for (int j = 0; j < 8; j++)
        split_pack(ws[kg * 16 + 2 * j][kk], ws[kg * 16 + 2 * j + 1][kk],
                   hi[j], lo[j]);
    size_t off = (size_t)(nb * 64 + kk) * DM + k0 + kg * 16;
    uint16_t* dh = (uint16_t*)g_Whi[z];
    uint16_t* dl = (uint16_t*)g_Wlo[z];
    *reinterpret_cast<uint4*>(dh + off)     = make_uint4(hi[0], hi[1], hi[2], hi[3]);
    *reinterpret_cast<uint4*>(dh + off + 8) = make_uint4(hi[4], hi[5], hi[6], hi[7]);
    *reinterpret_cast<uint4*>(dl + off)     = make_uint4(lo[0], lo[1], lo[2], lo[3]);
    *reinterpret_cast<uint4*>(dl + off + 8) = make_uint4(lo[4], lo[5], lo[6], lo[7]);
}

__global__ void vt_kernel() {
    __shared__ uint16_t tile[2][64][72];
    const int t = threadIdx.x;
    const int h = blockIdx.y >> 2, b = blockIdx.y & 3, s0 = blockIdx.x * 64;

    #pragma unroll
    for (int i = 0; i < 4; i++) {
        int id = t + i * 256;
        int z = id >> 9, rid = id & 511;
        int row = rid >> 3, c8 = rid & 7;
        const uint16_t* src = (const uint16_t*)(z ? g_Vlo : g_Vhi);
        uint4 v = *reinterpret_cast<const uint4*>(
            src + (size_t)(b * SEQ + s0 + row) * DM + h * DK + c8 * 8);
        *reinterpret_cast<uint4*>(&tile[z][row][c8 * 8]) = v;
    }
    __syncthreads();
    #pragma unroll
    for (int i = 0; i < 4; i++) {
        int id = t + i * 256;
        int z = id >> 9, rid = id & 511;
        int dk = rid >> 3, sc = rid & 7;
        uint32_t u[4];
        #pragma unroll
        for (int j = 0; j < 4; j++) {
            uint32_t a = tile[z][sc * 8 + 2 * j][dk];
            uint32_t c = tile[z][sc * 8 + 2 * j + 1][dk];
            u[j] = a | (c << 16);
        }
        uint16_t* dst = (uint16_t*)(z ? g_Vtlo : g_Vthi);
        *reinterpret_cast<uint4*>(
            dst + (size_t)((h * BATCH + b) * DK + dk) * SEQ + s0 + sc * 8) =
            make_uint4(u[0], u[1], u[2], u[3]);
    }
}

// ---------------------------------------------------------------------------
// mma.sync split-bf16 GEMM: 2-stage pipeline, 2 CTAs/SM.
// ---------------------------------------------------------------------------
#define BK 32
#define NKC (DM / BK)
#define TILE_B  (128 * 80)
#define STAGE_B (4 * TILE_B)
#define GEMM_SMEM (2 * STAGE_B)   // 81920

__device__ __forceinline__ void gemm_issue(uint32_t tb, const bf16* lsrc,
                                           int lr0, int lt, int k0) {
    #pragma unroll
    for (int c = 0; c < 8; c++) {
        int ch = lt + c * 64;
        int row = ch >> 2, kc = ch & 3;
        CP_ASYNC16(tb + row * 80 + kc * 16,
                   lsrc + (size_t)(lr0 + row) * DM + k0 + kc * 8);
    }
}

__global__ void __launch_bounds__(256, 2)
gemm_mma(int base_sel, float* __restrict__ out_ptr) {
    extern __shared__ char smem[];
    const int sel = base_sel + blockIdx.z;

    const bf16* Ah; const bf16* Al;
    bf16* Oh = nullptr; bf16* Ol = nullptr;
    if (sel == 0)      { Ah = g_Ahi[0]; Al = g_Alo[0]; Oh = g_Qhi; Ol = g_Qlo; }
    else if (sel == 1) { Ah = g_Ahi[1]; Al = g_Alo[1]; Oh = g_Khi; Ol = g_Klo; }
    else if (sel == 2) { Ah = g_Ahi[2]; Al = g_Alo[2]; Oh = g_Vhi; Ol = g_Vlo; }
    else               { Ah = g_Chi;    Al = g_Clo; }
    const bf16* Bh = g_Whi[sel];
    const bf16* Bl = g_Wlo[sel];

    const uint32_t sb = smem_u32(smem);
    const int tid = threadIdx.x;
    const int wid = tid >> 5, lane = tid & 31;
    const int m0 = blockIdx.y * 128, n0 = blockIdx.x * 128;
    const int wm = (wid & 1) * 64;
    const int wn = (wid >> 1) * 32;

    const int lt_tile = tid >> 6;
    const int lt = tid & 63;
    const bf16* lsrc = (lt_tile == 0) ? Ah : (lt_tile == 1) ? Al
                     : (lt_tile == 2) ? Bh : Bl;
    const int lr0 = (lt_tile >= 2) ? n0 : m0;
    const uint32_t ltb = sb + lt_tile * TILE_B;

    float acc[4][4][4];
    #pragma unroll
    for (int i = 0; i < 4; i++)
        #pragma unroll
        for (int j = 0; j < 4; j++)
            #pragma unroll
            for (int e = 0; e < 4; e++) acc[i][j][e] = 0.f;

    gemm_issue(ltb, lsrc, lr0, lt, 0);
    CP_COMMIT();

    for (int kch = 0; kch < NKC; kch++) {
        if (kch + 1 < NKC) {
            gemm_issue(ltb + ((kch + 1) & 1) * STAGE_B, lsrc, lr0, lt,
                       (kch + 1) * BK);
            CP_COMMIT();
            CP_WAIT(1);
        } else {
            CP_WAIT(0);
        }
        __syncthreads();

        const uint32_t stage = sb + (kch & 1) * STAGE_B;
        const uint32_t sAh = stage;
        const uint32_t sAl = stage + TILE_B;
        const uint32_t sBh = stage + 2 * TILE_B;
        const uint32_t sBl = stage + 3 * TILE_B;

        #pragma unroll
        for (int ks = 0; ks < 2; ks++) {
            uint32_t ah[4][4], al[4][4];
            #pragma unroll
            for (int mi = 0; mi < 4; mi++) {
                uint32_t ra = (uint32_t)(wm + mi * 16 + (lane & 15)) * 80
                            + ks * 32 + (lane >> 4) * 16;
                ldm_x4(ah[mi], sAh + ra);
                ldm_x4(al[mi], sAl + ra);
            }
            #pragma unroll
            for (int nj = 0; nj < 4; nj++) {
                uint32_t bh[2], bl[2];
                uint32_t rb = (uint32_t)(wn + nj * 8 + (lane & 7)) * 80
                            + ks * 32 + ((lane >> 3) & 1) * 16;
                ldm_x2(bh, sBh + rb);
                ldm_x2(bl, sBl + rb);
                #pragma unroll
                for (int mi = 0; mi < 4; mi++) {
                    mma16816(acc[mi][nj], ah[mi], bh);
                    mma16816(acc[mi][nj], ah[mi], bl);
                    mma16816(acc[mi][nj], al[mi], bh);
                }
            }
        }
        __syncthreads();
    }

    if (sel < 3) {
        uint16_t* oh = (uint16_t*)Oh;
        uint16_t* ol = (uint16_t*)Ol;
        #pragma unroll
        for (int mi = 0; mi < 4; mi++) {
            int row = m0 + wm + mi * 16 + (lane >> 2);
            #pragma unroll
            for (int nj = 0; nj < 4; nj++) {
                int col = n0 + wn + nj * 8 + (lane & 3) * 2;
                uint32_t h0, l0v, h1, l1v;
                split_pack(acc[mi][nj][0], acc[mi][nj][1], h0, l0v);
                split_pack(acc[mi][nj][2], acc[mi][nj][3], h1, l1v);
                *reinterpret_cast<uint32_t*>(oh + (size_t)row * DM + col) = h0;
                *reinterpret_cast<uint32_t*>(ol + (size_t)row * DM + col) = l0v;
                *reinterpret_cast<uint32_t*>(oh + (size_t)(row + 8) * DM + col) = h1;
                *reinterpret_cast<uint32_t*>(ol + (size_t)(row + 8) * DM + col) = l1v;
            }
        }
    } else {
        #pragma unroll
        for (int mi = 0; mi < 4; mi++) {
            int row = m0 + wm + mi * 16 + (lane >> 2);
            #pragma unroll
            for (int nj = 0; nj < 4; nj++) {
                int col = n0 + wn + nj * 8 + (lane & 3) * 2;
                *reinterpret_cast<float2*>(out_ptr + (size_t)row * DM + col) =
                    make_float2(acc[mi][nj][0], acc[mi][nj][1]);
                *reinterpret_cast<float2*>(out_ptr + (size_t)(row + 8) * DM + col) =
                    make_float2(acc[mi][nj][2], acc[mi][nj][3]);
            }
        }
    }
}

// ---------------------------------------------------------------------------
// Tensor-core fused attention, 3-stage KV pipeline, bit-packed mask.
// ---------------------------------------------------------------------------
#define SQH 0
#define SQL 18432
#define STAGE0 36864
#define STAGE_SZ 36864
#define OKH 0
#define OKL 9216
#define OVH 18432
#define OVL 27648
#define ATTN_SMEM (36864 + 3 * 36864)   // 147456
#define NEGINF (-INFINITY)

__device__ __forceinline__ void issue_kv(uint32_t stg, int kt0, int h, int b,
                                         int tid) {
    const int tile = tid >> 6, lt = tid & 63;
    if (tile < 2) {
        const bf16* s = tile ? g_Klo : g_Khi;
        uint32_t dstb = stg + (tile ? OKL : OKH);
        #pragma unroll
        for (int i = 0; i < 8; i++) {
            int row = (lt >> 3) + i * 8, col = lt & 7;
            CP_ASYNC16(dstb + row * 144 + col * 16,
                       s + (size_t)(b * SEQ + kt0 + row) * DM + h * DK + col * 8);
        }
    } else {
        const bf16* s = (tile == 3) ? g_Vtlo : g_Vthi;
        uint32_t dstb = stg + ((tile == 3) ? OVL : OVH);
        #pragma unroll
        for (int i = 0; i < 8; i++) {
            int row = (lt >> 3) + i * 8, col = lt & 7;
            CP_ASYNC16(dstb + row * 144 + col * 16,
                       s + (size_t)((h * BATCH + b) * DK + row) * SEQ + kt0 + col * 8);
        }
    }
}

__global__ void __launch_bounds__(256, 1)
attn_tc(float* __restrict__ scores_out) {
    extern __shared__ char smc[];
    const uint32_t sb = smem_u32(smc);
    const int tid = threadIdx.x, lane = tid & 31, w = tid >> 5;
    const int h = blockIdx.y, b = blockIdx.z;
    const int q0 = blockIdx.x * 128;
    const int g = lane >> 2, tg = lane & 3;

    {
        const int zt = tid >> 7, lt = tid & 127;
        const bf16* src = zt ? g_Qlo : g_Qhi;
        uint32_t dstb = sb + (zt ? SQL : SQH);
        #pragma unroll
        for (int i = 0; i < 8; i++) {
            int row = (lt >> 3) + i * 16, col = lt & 7;
            CP_ASYNC16(dstb + row * 144 + col * 16,
                       src + (size_t)(b * SEQ + q0 + row) * DM + h * DK + col * 8);
        }
    }
    issue_kv(sb + STAGE0, 0, h, b, tid);
    CP_COMMIT();
    issue_kv(sb + STAGE0 + STAGE_SZ, 64, h, b, tid);
    CP_COMMIT();

    uint32_t qh[4][4], ql[4][4];
    float O[8][4];
    #pragma unroll
    for (int nj = 0; nj < 8; nj++)
        #pragma unroll
        for (int e = 0; e < 4; e++) O[nj][e] = 0.f;
    float m0 = NEGINF, m1 = NEGINF, l0 = 0.f, l1 = 0.f;

    const int qr0 = q0 + w * 16 + g;
    const uint32_t* mrow = g_maskbits + ((size_t)(b * SEQ + qr0)) * 32;

    int sidx = 0;
    for (int kt = 0; kt < 16; kt++) {
        if (kt + 1 < 16) { CP_WAIT(1); } else { CP_WAIT(0); }
        __syncthreads();
        if (kt + 2 < 16) {
            int si2 = sidx + 2; if (si2 >= 3) si2 -= 3;
            issue_kv(sb + STAGE0 + si2 * STAGE_SZ, (kt + 2) * 64, h, b, tid);
            CP_COMMIT();
        }

        if (kt == 0) {
            #pragma unroll
            for (int ks = 0; ks < 4; ks++) {
                uint32_t ra = sb + SQH + (uint32_t)(w * 16 + (lane & 15)) * 144
                            + ks * 32 + (lane >> 4) * 16;
                ldm_x4(qh[ks], ra);
                ldm_x4(ql[ks], ra + (SQL - SQH));
            }
        }

        const uint32_t stg = sb + STAGE0 + sidx * STAGE_SZ;
        float s[8][4];

        #pragma unroll
        for (int njp = 0; njp < 4; njp++) {
            #pragma unroll
            for (int e = 0; e < 4; e++) { s[2*njp][e] = 0.f; s[2*njp+1][e] = 0.f; }
            #pragma unroll
            for (int ks = 0; ks < 4; ks++) {
                uint32_t kh4[4], kl4[4];
                uint32_t ad = stg + OKH
                    + (uint32_t)(njp * 16 + ((lane >> 4) & 1) * 8 + (lane & 7)) * 144
                    + ks * 32 + ((lane >> 3) & 1) * 16;
                ldm_x4(kh4, ad);
                ldm_x4(kl4, ad + (OKL - OKH));
                mma16816(s[2*njp],   qh[ks], kh4);
                mma16816(s[2*njp],   qh[ks], kl4);
                mma16816(s[2*njp],   ql[ks], kh4);
                mma16816(s[2*njp+1], qh[ks], kh4 + 2);
                mma16816(s[2*njp+1], qh[ks], kl4 + 2);
                mma16816(s[2*njp+1], ql[ks], kh4 + 2);
            }
        }

        const int kt0 = kt * 64;
        const uint32_t w0a = mrow[kt * 2],       w0b = mrow[kt * 2 + 1];
        const uint32_t w1a = mrow[256 + kt * 2], w1b = mrow[256 + kt * 2 + 1];
        float* so0 = scores_out + ((size_t)((h * BATCH + b) * SEQ + qr0)) * SEQ + kt0;
        float* so1 = so0 + 8 * SEQ;
        #pragma unroll
        for (int nj = 0; nj < 8; nj++) {
            int c = nj * 8 + tg * 2;
            uint32_t wr0 = (nj < 4) ? w0a : w0b;
            uint32_t wr1 = (nj < 4) ? w1a : w1b;
            int sh = c & 31;
            s[nj][0] = ((wr0 >> sh) & 1)       ? s[nj][0] * 0.125f : NEGINF;
            s[nj][1] = ((wr0 >> (sh + 1)) & 1) ? s[nj][1] * 0.125f : NEGINF;
            s[nj][2] = ((wr1 >> sh) & 1)       ? s[nj][2] * 0.125f : NEGINF;
            s[nj][3] = ((wr1 >> (sh + 1)) & 1) ? s[nj][3] * 0.125f : NEGINF;
            *reinterpret_cast<float2*>(so0 + c) = make_float2(s[nj][0], s[nj][1]);
            *reinterpret_cast<float2*>(so1 + c) = make_float2(s[nj][2], s[nj][3]);
        }

        float rm0 = NEGINF, rm1 = NEGINF;
        #pragma unroll
        for (int nj = 0; nj < 8; nj++) {
            rm0 = fmaxf(rm0, fmaxf(s[nj][0], s[nj][1]));
            rm1 = fmaxf(rm1, fmaxf(s[nj][2], s[nj][3]));
        }
        rm0 = fmaxf(rm0, __shfl_xor_sync(0xffffffffu, rm0, 1));
        rm0 = fmaxf(rm0, __shfl_xor_sync(0xffffffffu, rm0, 2));
        rm1 = fmaxf(rm1, __shfl_xor_sync(0xffffffffu, rm1, 1));
        rm1 = fmaxf(rm1, __shfl_xor_sync(0xffffffffu, rm1, 2));

        float mn0 = fmaxf(m0, rm0), mn1 = fmaxf(m1, rm1);
        float mu0 = fmaxf(mn0, -1e30f), mu1 = fmaxf(mn1, -1e30f);
        float c0 = __expf(fmaxf(m0, -1e30f) - mu0);
        float c1 = __expf(fmaxf(m1, -1e30f) - mu1);
        m0 = mn0; m1 = mn1;

        float rs0 = 0.f, rs1 = 0.f;
        #pragma unroll
        for (int nj = 0; nj < 8; nj++) {
            s[nj][0] = __expf(s[nj][0] - mu0);
            s[nj][1] = __expf(s[nj][1] - mu0);
            s[nj][2] = __expf(s[nj][2] - mu1);
            s[nj][3] = __expf(s[nj][3] - mu1);
            rs0 += s[nj][0] + s[nj][1];
            rs1 += s[nj][2] + s[nj][3];
        }
        rs0 += __shfl_xor_sync(0xffffffffu, rs0, 1);
        rs0 += __shfl_xor_sync(0xffffffffu, rs0, 2);
        rs1 += __shfl_xor_sync(0xffffffffu, rs1, 1);
        rs1 += __shfl_xor_sync(0xffffffffu, rs1, 2);
        l0 = l0 * c0 + rs0;
        l1 = l1 * c1 + rs1;

        #pragma unroll
        for (int nj = 0; nj < 8; nj++) {
            O[nj][0] *= c0; O[nj][1] *= c0;
            O[nj][2] *= c1; O[nj][3] *= c1;
        }

        uint32_t ph[4][4], pl[4][4];
        #pragma unroll
        for (int ks = 0; ks < 4; ks++) {
            split_pack(s[2*ks][0],   s[2*ks][1],   ph[ks][0], pl[ks][0]);
            split_pack(s[2*ks][2],   s[2*ks][3],   ph[ks][1], pl[ks][1]);
            split_pack(s[2*ks+1][0], s[2*ks+1][1], ph[ks][2], pl[ks][2]);
            split_pack(s[2*ks+1][2], s[2*ks+1][3], ph[ks][3], pl[ks][3]);
        }

        #pragma unroll
        for (int ks = 0; ks < 4; ks++) {
            #pragma unroll
            for (int njp = 0; njp < 4; njp++) {
                uint32_t vh4[4], vl4[4];
                uint32_t ad = stg + OVH
                    + (uint32_t)(njp * 16 + ((lane >> 4) & 1) * 8 + (lane & 7)) * 144
                    + ks * 32 + ((lane >> 3) & 1) * 16;
                ldm_x4(vh4, ad);
                ldm_x4(vl4, ad + (OVL - OVH));
                mma16816(O[2*njp],   ph[ks], vh4);
                mma16816(O[2*njp],   ph[ks], vl4);
                mma16816(O[2*njp],   pl[ks], vh4);
                mma16816(O[2*njp+1], ph[ks], vh4 + 2);
                mma16816(O[2*njp+1], ph[ks], vl4 + 2);
                mma16816(O[2*njp+1], pl[ks], vh4 + 2);
            }
        }
        sidx++; if (sidx == 3) sidx = 0;
    }

    float inv0 = 1.f / l0, inv1 = 1.f / l1;
    uint16_t* ch = (uint16_t*)g_Chi;
    uint16_t* cl = (uint16_t*)g_Clo;
    size_t base0 = (size_t)(b * SEQ + qr0) * DM + h * DK;
    size_t base1 = base0 + (size_t)8 * DM;
    #pragma unroll
    for (int nj = 0; nj < 8; nj++) {
        int c = nj * 8 + tg * 2;
        uint32_t h0, l0v, h1, l1v;
        split_pack(O[nj][0] * inv0, O[nj][1] * inv0, h0, l0v);
        split_pack(O[nj][2] * inv1, O[nj][3] * inv1, h1, l1v);
        *reinterpret_cast<uint32_t*>(ch + base0 + c) = h0;
        *reinterpret_cast<uint32_t*>(cl + base0 + c) = l0v;
        *reinterpret_cast<uint32_t*>(ch + base1 + c) = h1;
        *reinterpret_cast<uint32_t*>(cl + base1 + c) = l1v;
    }
}

// ---------------------------------------------------------------------------
extern "C" void kernel_launch(void* const* d_in, const int* in_sizes, int n_in,
                              void* d_out, int out_size) {
    const float* q    = (const float*)d_in[0];
    const float* k    = (const float*)d_in[1];
    const float* v    = (const float*)d_in[2];
    const int*   mask = (const int*)  d_in[3];
    const float* Wq   = (const float*)d_in[4];
    const float* Wk   = (const float*)d_in[5];
    const float* Wv   = (const float*)d_in[6];
    const float* Wo   = (const float*)d_in[7];

    float* out    = (float*)d_out;
    float* scores = out + OUT_OFF;

    cudaFuncSetAttribute(gemm_mma,
                         cudaFuncAttributeMaxDynamicSharedMemorySize, GEMM_SMEM);
    cudaFuncSetAttribute(attn_tc,
                         cudaFuncAttributeMaxDynamicSharedMemorySize, ATTN_SMEM);

    maskpack_kernel<<<M_ROWS / 8, 256>>>(mask);
    split3_kernel<<<dim3(M_ROWS * DM / 1024, 1, 3), 256>>>(q, k, v);
    prep_w_kernel<<<dim3(16, 16, 4), 256>>>(Wq, Wk, Wv, Wo);
    gemm_mma<<<dim3(DM / 128, M_ROWS / 128, 3), 256, GEMM_SMEM>>>(0, nullptr);
    vt_kernel<<<dim3(16, 64), 256>>>();
    attn_tc<<<dim3(SEQ / 128, H, BATCH), 256, ATTN_SMEM>>>(scores);
    gemm_mma<<<dim3(DM / 128, M_ROWS / 128, 1), 256, GEMM_SMEM>>>(3, out);
}